// round 11
// baseline (speedup 1.0000x reference)
#include <cuda_runtime.h>
#include <cuda_bf16.h>
#include <stdint.h>
#include <math.h>

#define BATCH 4
#define SEQ   4096
#define EMB   1024
#define HD    64
#define MTOT  (BATCH*SEQ)

// bf16 hi/lo projected Q,K,V (device globals: allocation-rule-safe)
__device__ __nv_bfloat16 g_qh[MTOT*HD];
__device__ __nv_bfloat16 g_ql[MTOT*HD];
__device__ __nv_bfloat16 g_kh[MTOT*HD];
__device__ __nv_bfloat16 g_kl[MTOT*HD];
__device__ __nv_bfloat16 g_vh[MTOT*HD];
__device__ __nv_bfloat16 g_vl[MTOT*HD];

// Split-K attention partials: 160 chunks per batch, 640 total.
// Per chunk: O 64x64 f32 (unnormalized), m[64], l[64].
#define NXC 160
#define NCHUNK (BATCH*NXC)
__device__ float g_po[NCHUNK*64*64];
__device__ float g_pm[NCHUNK*64];
__device__ float g_pl[NCHUNK*64];

// Single extern shared symbol (char) — cast per kernel.
extern __shared__ char hx_smem[];

// ---------------------------------------------------------------------------
// Helpers
// ---------------------------------------------------------------------------
__device__ __forceinline__ uint32_t smem_u32(const void* p) {
    uint32_t a;
    asm("{ .reg .u64 t; cvta.to.shared.u64 t, %1; cvt.u32.u64 %0, t; }"
        : "=r"(a) : "l"(p));
    return a;
}

__device__ __forceinline__ void ldsm_x4(uint32_t* r, uint32_t addr) {
    asm volatile("ldmatrix.sync.aligned.m8n8.x4.shared.b16 {%0,%1,%2,%3}, [%4];"
        : "=r"(r[0]), "=r"(r[1]), "=r"(r[2]), "=r"(r[3]) : "r"(addr));
}
__device__ __forceinline__ void ldsm_x4_t(uint32_t* r, uint32_t addr) {
    asm volatile("ldmatrix.sync.aligned.m8n8.x4.trans.shared.b16 {%0,%1,%2,%3}, [%4];"
        : "=r"(r[0]), "=r"(r[1]), "=r"(r[2]), "=r"(r[3]) : "r"(addr));
}

// D += A @ B : m16n8k16, bf16 in, fp32 accum
__device__ __forceinline__ void mma16816(float* d, const uint32_t* a,
                                         const uint32_t* b) {
    asm volatile("mma.sync.aligned.m16n8k16.row.col.f32.bf16.bf16.f32 "
        "{%0,%1,%2,%3}, {%4,%5,%6,%7}, {%8,%9}, {%0,%1,%2,%3};"
        : "+f"(d[0]), "+f"(d[1]), "+f"(d[2]), "+f"(d[3])
        : "r"(a[0]), "r"(a[1]), "r"(a[2]), "r"(a[3]), "r"(b[0]), "r"(b[1]));
}

__device__ __forceinline__ uint32_t pack_bf2(float a, float b) {
    __nv_bfloat162 t = __floats2bfloat162_rn(a, b);
    return *(uint32_t*)&t;
}

// chunk-table helpers: chunks of 16 key tiles per q-tile
__device__ __forceinline__ int chunk_base(int qt) {
    if (qt < 16) return qt;
    if (qt < 32) return 16 + 2 * (qt - 16);
    if (qt < 48) return 48 + 3 * (qt - 32);
    return 96 + 4 * (qt - 48);
}

// ---------------------------------------------------------------------------
// Kernel 1: QKV projection via warp-level bf16 MMA with hi/lo split.
// BM=64 rows/CTA, 128 threads (4 warps x 16 rows), grid 256. BK=64.
// ---------------------------------------------------------------------------
#define BROW 144                       // bytes per smem row (64 bf16 + pad)
#define QOFF_AH 0
#define QOFF_AL (64*BROW)              // 9216
#define QOFF_B  (2*64*BROW)            // 18432; 6 tiles of 64*BROW=9216
#define BTILE   (64*BROW)
#define QKV_SMEM (QOFF_B + 6*BTILE)    // 73728

__global__ __launch_bounds__(128) void qkv_mma(
    const float* __restrict__ x,
    const float* __restrict__ Wq,
    const float* __restrict__ Wk,
    const float* __restrict__ Wv)
{
    char* smem = hx_smem;
    const uint32_t sb = smem_u32(smem);
    const int tid  = threadIdx.x;
    const int wid  = tid >> 5;
    const int lane = tid & 31;
    const int m0   = blockIdx.x * 64;

    const float* Ws[3] = {Wq, Wk, Wv};

    // ldmatrix lane address components
    const int a_row  = lane & 15;
    const int a_koff = (lane >> 4) * 8;          // bf16 elems
    const int b_q    = lane >> 3;
    const int b_r    = lane & 7;
    const int b_nloc = (b_q >> 1) * 8 + b_r;     // n within 16-wide pair
    const int b_koff = (b_q & 1) * 8;

    float acc[3][8][4] = {};

    // W-loader: thread owns n pair (n2, n2+1), k stripe wk + 4i
    const int n2 = (tid & 31) * 2;
    const int wk = tid >> 5;        // 0..3

    #pragma unroll 1
    for (int c = 0; c < 16; c++) {
        __syncthreads();   // previous chunk's LDSM reads complete

        // ---- A chunk: X[m0..+63][c*64..+63] -> hi/lo bf16 smem ----
        #pragma unroll
        for (int i = 0; i < 8; i++) {
            int j  = tid + i * 128;          // 0..1023 float4s
            int r  = j >> 4;
            int c4 = (j & 15) * 4;
            float4 v = *(const float4*)(x + (size_t)(m0 + r) * EMB + c * 64 + c4);
            __nv_bfloat16 h0 = __float2bfloat16(v.x);
            __nv_bfloat16 h1 = __float2bfloat16(v.y);
            __nv_bfloat16 h2 = __float2bfloat16(v.z);
            __nv_bfloat16 h3 = __float2bfloat16(v.w);
            __nv_bfloat162 hA = {h0, h1}, hB = {h2, h3};
            __nv_bfloat162 lA = {__float2bfloat16(v.x - __bfloat162float(h0)),
                                 __float2bfloat16(v.y - __bfloat162float(h1))};
            __nv_bfloat162 lB = {__float2bfloat16(v.z - __bfloat162float(h2)),
                                 __float2bfloat16(v.w - __bfloat162float(h3))};
            uint32_t off = (uint32_t)(r * BROW + c4 * 2);
            *(uint2*)(smem + QOFF_AH + off) =
                make_uint2(*(uint32_t*)&hA, *(uint32_t*)&hB);
            *(uint2*)(smem + QOFF_AL + off) =
                make_uint2(*(uint32_t*)&lA, *(uint32_t*)&lB);
        }

        // ---- B chunks: W[c*64+k][n] -> Bs[n][k] hi/lo bf16 ----
        #pragma unroll
        for (int o = 0; o < 3; o++) {
            const float* W = Ws[o];
            char* bh = smem + QOFF_B + (o * 2 + 0) * BTILE;
            char* bl = smem + QOFF_B + (o * 2 + 1) * BTILE;
            #pragma unroll 4
            for (int i = 0; i < 16; i++) {
                int kl = i * 4 + wk;
                float2 f = *(const float2*)&W[(size_t)(c * 64 + kl) * HD + n2];
                __nv_bfloat16 ha = __float2bfloat16(f.x);
                __nv_bfloat16 hb = __float2bfloat16(f.y);
                __nv_bfloat16 la = __float2bfloat16(f.x - __bfloat162float(ha));
                __nv_bfloat16 lb = __float2bfloat16(f.y - __bfloat162float(hb));
                uint32_t offa = (uint32_t)(n2 * BROW + kl * 2);
                *(__nv_bfloat16*)(bh + offa)        = ha;
                *(__nv_bfloat16*)(bh + offa + BROW) = hb;
                *(__nv_bfloat16*)(bl + offa)        = la;
                *(__nv_bfloat16*)(bl + offa + BROW) = lb;
            }
        }
        __syncthreads();

        // ---- A fragments: 2 splits x 4 k-steps ----
        uint32_t afr[2][4][4];
        #pragma unroll
        for (int spl = 0; spl < 2; spl++)
            #pragma unroll
            for (int s = 0; s < 4; s++)
                ldsm_x4(afr[spl][s],
                        sb + (spl ? QOFF_AL : QOFF_AH) +
                        (uint32_t)((wid * 16 + a_row) * BROW +
                                   (s * 16 + a_koff) * 2));

        // ---- MMAs: Xh@Wh + Xl@Wh + Xh@Wl ----
        #pragma unroll
        for (int o = 0; o < 3; o++) {
            uint32_t bhb = sb + QOFF_B + (o * 2 + 0) * BTILE;
            uint32_t blb = sb + QOFF_B + (o * 2 + 1) * BTILE;
            #pragma unroll
            for (int s = 0; s < 4; s++) {
                #pragma unroll
                for (int p = 0; p < 4; p++) {
                    uint32_t boff = (uint32_t)((p * 16 + b_nloc) * BROW +
                                               (s * 16 + b_koff) * 2);
                    uint32_t bf[4];
                    ldsm_x4(bf, bhb + boff);
                    mma16816(acc[o][2*p],   afr[0][s], bf);
                    mma16816(acc[o][2*p+1], afr[0][s], bf + 2);
                    mma16816(acc[o][2*p],   afr[1][s], bf);
                    mma16816(acc[o][2*p+1], afr[1][s], bf + 2);
                    ldsm_x4(bf, blb + boff);
                    mma16816(acc[o][2*p],   afr[0][s], bf);
                    mma16816(acc[o][2*p+1], afr[0][s], bf + 2);
                }
            }
        }
    }

    // ---- epilogue: c-frags -> bf16 hi/lo globals ----
    __nv_bfloat16* OH[3] = {g_qh, g_kh, g_vh};
    __nv_bfloat16* OL[3] = {g_ql, g_kl, g_vl};
    const int g  = lane >> 2;
    const int tg = lane & 3;
    #pragma unroll
    for (int o = 0; o < 3; o++) {
        #pragma unroll
        for (int nt = 0; nt < 8; nt++) {
            int mrow = m0 + wid * 16 + g;
            int ncol = nt * 8 + tg * 2;
            float c0 = acc[o][nt][0], c1 = acc[o][nt][1];
            float c2 = acc[o][nt][2], c3 = acc[o][nt][3];
            __nv_bfloat162 h01 = __floats2bfloat162_rn(c0, c1);
            __nv_bfloat162 h23 = __floats2bfloat162_rn(c2, c3);
            __nv_bfloat162 l01 = __floats2bfloat162_rn(
                c0 - __bfloat162float(h01.x), c1 - __bfloat162float(h01.y));
            __nv_bfloat162 l23 = __floats2bfloat162_rn(
                c2 - __bfloat162float(h23.x), c3 - __bfloat162float(h23.y));
            *(uint32_t*)&OH[o][(size_t)mrow * HD + ncol]       = *(uint32_t*)&h01;
            *(uint32_t*)&OL[o][(size_t)mrow * HD + ncol]       = *(uint32_t*)&l01;
            *(uint32_t*)&OH[o][(size_t)(mrow + 8) * HD + ncol] = *(uint32_t*)&h23;
            *(uint32_t*)&OL[o][(size_t)(mrow + 8) * HD + ncol] = *(uint32_t*)&l23;
        }
    }
}

// ---------------------------------------------------------------------------
// Kernel 2: split-K chunked flash attention on HMMA.
// Grid (160, 4): each CTA handles <=16 key tiles of one q-tile, writes
// unnormalized partial (O, m, l) to scratch. 128 threads = 4 warps x 16 rows.
// ---------------------------------------------------------------------------
#define ABROW 144
#define ATILE (64*ABROW)          // 9216 bytes per tile array
#define ATTN_SMEM (4*ATILE)       // Kh,Kl,Vh,Vl = 36864

__global__ __launch_bounds__(128) void attn_chunk()
{
    char* smem = hx_smem;
    const uint32_t sb = smem_u32(smem);
    const int tid  = threadIdx.x;
    const int wid  = tid >> 5;
    const int lane = tid & 31;
    const int g    = lane >> 2;
    const int tg   = lane & 3;

    // big-qt chunks first (LPT)
    const int x = (NXC - 1) - (int)blockIdx.x;
    const int b = blockIdx.y;
    int qt, c;
    if (x < 16)      { qt = x;                 c = 0; }
    else if (x < 48) { qt = 16 + (x - 16) / 2; c = (x - 16) & 1; }
    else if (x < 96) { qt = 32 + (x - 48) / 3; c = (x - 48) % 3; }
    else             { qt = 48 + (x - 96) / 4; c = (x - 96) & 3; }

    const int jt0 = c * 16;
    const int jt1 = min(qt + 1, jt0 + 16);
    const int r0  = qt * 64;
    const size_t tb = (size_t)b * SEQ;

    // ldmatrix lane addressing
    const int lq  = lane >> 3, lr = lane & 7;
    const int bn  = (lq >> 1) * 8 + lr;       // non-trans B: n row
    const int bk  = (lq & 1) * 8;             //               k offset
    const int trr = (lq & 1) * 8 + lr;        // trans: source row (k)
    const int trc = (lq >> 1) * 8;            //        source col (n)

    const int row_a = r0 + wid * 16 + g;      // global rows this thread owns
    const int row_b = row_a + 8;

    // ---- Q a-frags (hi/lo), loaded once from gmem ----
    uint32_t aQh[4][4], aQl[4][4];
    #pragma unroll
    for (int ks = 0; ks < 4; ks++) {
        size_t ra = (tb + row_a) * HD + ks * 16 + 2 * tg;
        size_t rb = (tb + row_b) * HD + ks * 16 + 2 * tg;
        aQh[ks][0] = *(const uint32_t*)&g_qh[ra];
        aQh[ks][1] = *(const uint32_t*)&g_qh[rb];
        aQh[ks][2] = *(const uint32_t*)&g_qh[ra + 8];
        aQh[ks][3] = *(const uint32_t*)&g_qh[rb + 8];
        aQl[ks][0] = *(const uint32_t*)&g_ql[ra];
        aQl[ks][1] = *(const uint32_t*)&g_ql[rb];
        aQl[ks][2] = *(const uint32_t*)&g_ql[ra + 8];
        aQl[ks][3] = *(const uint32_t*)&g_ql[rb + 8];
    }

    float oacc[8][4] = {};
    float mA = -1e30f, mB = -1e30f, lA = 0.0f, lB = 0.0f;

    const __nv_bfloat16* bases[4] = {g_kh + tb * HD, g_kl + tb * HD,
                                     g_vh + tb * HD, g_vl + tb * HD};

    for (int jt = jt0; jt < jt1; jt++) {
        const int s0 = jt * 64;
        __syncthreads();
        // ---- stage Kh,Kl,Vh,Vl tiles (64x64 bf16 each) ----
        {
            const int lrow = tid >> 3, lseg = tid & 7;
            #pragma unroll
            for (int i = 0; i < 16; i++) {
                int arr = i >> 2;
                int row = (i & 3) * 16 + lrow;
                *(uint4*)(smem + arr * ATILE + row * ABROW + lseg * 16) =
                    *(const uint4*)(bases[arr] + (size_t)(s0 + row) * HD + lseg * 8);
            }
        }
        __syncthreads();

        // ---- S = Q K^T (3-term hi/lo) ----
        float sacc[8][4] = {};
        #pragma unroll
        for (int ks = 0; ks < 4; ks++) {
            #pragma unroll
            for (int np = 0; np < 4; np++) {
                uint32_t boff = (uint32_t)((np * 16 + bn) * ABROW +
                                           (ks * 16 + bk) * 2);
                uint32_t bh[4], bl[4];
                ldsm_x4(bh, sb + 0 * ATILE + boff);
                ldsm_x4(bl, sb + 1 * ATILE + boff);
                mma16816(sacc[2*np],   aQh[ks], bh);
                mma16816(sacc[2*np+1], aQh[ks], bh + 2);
                mma16816(sacc[2*np],   aQl[ks], bh);
                mma16816(sacc[2*np+1], aQl[ks], bh + 2);
                mma16816(sacc[2*np],   aQh[ks], bl);
                mma16816(sacc[2*np+1], aQh[ks], bl + 2);
            }
        }

        // ---- scale + causal mask (diag tile only) ----
        const float scale = 0.03125f;   // 1/sqrt(1024)
        if (jt == qt) {
            #pragma unroll
            for (int nt = 0; nt < 8; nt++) {
                int col = s0 + nt * 8 + 2 * tg;
                sacc[nt][0] = (col     > row_a) ? -1e30f : sacc[nt][0] * scale;
                sacc[nt][1] = (col + 1 > row_a) ? -1e30f : sacc[nt][1] * scale;
                sacc[nt][2] = (col     > row_b) ? -1e30f : sacc[nt][2] * scale;
                sacc[nt][3] = (col + 1 > row_b) ? -1e30f : sacc[nt][3] * scale;
            }
        } else {
            #pragma unroll
            for (int nt = 0; nt < 8; nt++) {
                sacc[nt][0] *= scale; sacc[nt][1] *= scale;
                sacc[nt][2] *= scale; sacc[nt][3] *= scale;
            }
        }

        // ---- online softmax ----
        float rmA = -1e30f, rmB = -1e30f;
        #pragma unroll
        for (int nt = 0; nt < 8; nt++) {
            rmA = fmaxf(rmA, fmaxf(sacc[nt][0], sacc[nt][1]));
            rmB = fmaxf(rmB, fmaxf(sacc[nt][2], sacc[nt][3]));
        }
        rmA = fmaxf(rmA, __shfl_xor_sync(0xffffffffu, rmA, 1));
        rmA = fmaxf(rmA, __shfl_xor_sync(0xffffffffu, rmA, 2));
        rmB = fmaxf(rmB, __shfl_xor_sync(0xffffffffu, rmB, 1));
        rmB = fmaxf(rmB, __shfl_xor_sync(0xffffffffu, rmB, 2));

        float mnA = fmaxf(mA, rmA), mnB = fmaxf(mB, rmB);
        float alA = __expf(mA - mnA), alB = __expf(mB - mnB);
        mA = mnA; mB = mnB;

        float rsA = 0.0f, rsB = 0.0f;
        uint32_t aPh[4][4], aPl[4][4];
        #pragma unroll
        for (int s4 = 0; s4 < 4; s4++) {
            #pragma unroll
            for (int j = 0; j < 2; j++) {
                int nt = 2 * s4 + j;
                float p0 = __expf(sacc[nt][0] - mA);
                float p1 = __expf(sacc[nt][1] - mA);
                float p2 = __expf(sacc[nt][2] - mB);
                float p3 = __expf(sacc[nt][3] - mB);
                rsA += p0 + p1; rsB += p2 + p3;
                __nv_bfloat162 h01 = __floats2bfloat162_rn(p0, p1);
                __nv_bfloat162 h23 = __floats2bfloat162_rn(p2, p3);
                aPh[s4][2*j]   = *(uint32_t*)&h01;
                aPh[s4][2*j+1] = *(uint32_t*)&h23;
                aPl[s4][2*j]   = pack_bf2(p0 - __bfloat162float(h01.x),
                                          p1 - __bfloat162float(h01.y));
                aPl[s4][2*j+1] = pack_bf2(p2 - __bfloat162float(h23.x),
                                          p3 - __bfloat162float(h23.y));
            }
        }
        rsA += __shfl_xor_sync(0xffffffffu, rsA, 1);
        rsA += __shfl_xor_sync(0xffffffffu, rsA, 2);
        rsB += __shfl_xor_sync(0xffffffffu, rsB, 1);
        rsB += __shfl_xor_sync(0xffffffffu, rsB, 2);
        lA = lA * alA + rsA;
        lB = lB * alB + rsB;

        #pragma unroll
        for (int ht = 0; ht < 8; ht++) {
            oacc[ht][0] *= alA; oacc[ht][1] *= alA;
            oacc[ht][2] *= alB; oacc[ht][3] *= alB;
        }

        // ---- O += P V (3-term hi/lo), V b-frags via ldmatrix.trans ----
        #pragma unroll
        for (int ks = 0; ks < 4; ks++) {
            #pragma unroll
            for (int hp = 0; hp < 4; hp++) {
                uint32_t taddr = sb + 2 * ATILE +
                    (uint32_t)((ks * 16 + trr) * ABROW + (hp * 16 + trc) * 2);
                uint32_t vh4[4], vl4[4];
                ldsm_x4_t(vh4, taddr);
                ldsm_x4_t(vl4, taddr + ATILE);
                mma16816(oacc[2*hp],   aPh[ks], vh4);
                mma16816(oacc[2*hp+1], aPh[ks], vh4 + 2);
                mma16816(oacc[2*hp],   aPl[ks], vh4);
                mma16816(oacc[2*hp+1], aPl[ks], vh4 + 2);
                mma16816(oacc[2*hp],   aPh[ks], vl4);
                mma16816(oacc[2*hp+1], aPh[ks], vl4 + 2);
            }
        }
    }

    // ---- store unnormalized partial (O, m, l) ----
    const int cid = b * NXC + x;
    float* po = g_po + (size_t)cid * 4096;
    const int la = wid * 16 + g;      // local row a
    #pragma unroll
    for (int ht = 0; ht < 8; ht++) {
        int col = ht * 8 + 2 * tg;
        *(float2*)&po[la * 64 + col]       = make_float2(oacc[ht][0], oacc[ht][1]);
        *(float2*)&po[(la + 8) * 64 + col] = make_float2(oacc[ht][2], oacc[ht][3]);
    }
    if (tg == 0) {
        g_pm[cid * 64 + la]     = mA;
        g_pm[cid * 64 + la + 8] = mB;
        g_pl[cid * 64 + la]     = lA;
        g_pl[cid * 64 + la + 8] = lB;
    }
}

// ---------------------------------------------------------------------------
// Kernel 3: merge partial chunks. Grid (64, 4) = (qt, b), 256 threads.
// Thread: row r = tid/4, cols (tid%4)*16 .. +15.
// ---------------------------------------------------------------------------
__global__ __launch_bounds__(256) void attn_merge(float* __restrict__ out)
{
    const int qt = blockIdx.x;
    const int b  = blockIdx.y;
    const int nc = qt / 16 + 1;
    const int base = chunk_base(qt);

    const int r  = threadIdx.x >> 2;
    const int q4 = threadIdx.x & 3;

    float m[4], l[4];
    float M = -1e30f;
    #pragma unroll 4
    for (int i = 0; i < nc; i++) {
        int cid = b * NXC + base + i;
        m[i] = g_pm[cid * 64 + r];
        l[i] = g_pl[cid * 64 + r];
        M = fmaxf(M, m[i]);
    }
    float denom = 0.0f;
    float w[4];
    #pragma unroll 4
    for (int i = 0; i < nc; i++) {
        w[i] = __expf(m[i] - M);
        denom += l[i] * w[i];
    }
    float inv = 1.0f / denom;

    float4 acc[4] = {};
    #pragma unroll 4
    for (int i = 0; i < nc; i++) {
        const float* po = g_po + (size_t)(b * NXC + base + i) * 4096 + r * 64 + q4 * 16;
        float wi = w[i];
        #pragma unroll
        for (int v = 0; v < 4; v++) {
            float4 t = *(const float4*)(po + v * 4);
            acc[v].x += t.x * wi; acc[v].y += t.y * wi;
            acc[v].z += t.z * wi; acc[v].w += t.w * wi;
        }
    }
    float* dst = out + ((size_t)b * SEQ + qt * 64 + r) * HD + q4 * 16;
    #pragma unroll
    for (int v = 0; v < 4; v++) {
        acc[v].x *= inv; acc[v].y *= inv; acc[v].z *= inv; acc[v].w *= inv;
        *(float4*)(dst + v * 4) = acc[v];
    }
}

// ---------------------------------------------------------------------------
extern "C" void kernel_launch(void* const* d_in, const int* in_sizes, int n_in,
                              void* d_out, int out_size)
{
    const float* x  = (const float*)d_in[0];
    const float* Wq = (const float*)d_in[1];
    const float* Wk = (const float*)d_in[2];
    const float* Wv = (const float*)d_in[3];
    float* out = (float*)d_out;

    cudaFuncSetAttribute(qkv_mma,
                         cudaFuncAttributeMaxDynamicSharedMemorySize, QKV_SMEM);

    qkv_mma<<<MTOT / 64, 128, QKV_SMEM>>>(x, Wq, Wk, Wv);
    attn_chunk<<<dim3(NXC, BATCH), 128, ATTN_SMEM>>>();
    attn_merge<<<dim3(64, BATCH), 256>>>(out);
}

// round 12
// speedup vs baseline: 1.4373x; 1.4373x over previous
#include <cuda_runtime.h>
#include <cuda_bf16.h>
#include <stdint.h>
#include <math.h>

#define BATCH 4
#define SEQ   4096
#define EMB   1024
#define HD    64
#define MTOT  (BATCH*SEQ)

// bf16 hi/lo projected Q,K,V (device globals: allocation-rule-safe)
__device__ __nv_bfloat16 g_qh[MTOT*HD];
__device__ __nv_bfloat16 g_ql[MTOT*HD];
__device__ __nv_bfloat16 g_kh[MTOT*HD];
__device__ __nv_bfloat16 g_kl[MTOT*HD];
__device__ __nv_bfloat16 g_vh[MTOT*HD];
__device__ __nv_bfloat16 g_vl[MTOT*HD];

// Pre-converted weights, TRANSPOSED: [o][n=64][k=1024], hi and lo.
__device__ __nv_bfloat16 g_wh[3*HD*EMB];
__device__ __nv_bfloat16 g_wl[3*HD*EMB];

// Split-K attention partials: 160 chunks per batch, 640 total.
#define NXC 160
#define NCHUNK (BATCH*NXC)
__device__ float g_po[NCHUNK*64*64];
__device__ float g_pm[NCHUNK*64];
__device__ float g_pl[NCHUNK*64];

// Single extern shared symbol (char) — cast per kernel.
extern __shared__ char hx_smem[];

// ---------------------------------------------------------------------------
// Helpers
// ---------------------------------------------------------------------------
__device__ __forceinline__ uint32_t smem_u32(const void* p) {
    uint32_t a;
    asm("{ .reg .u64 t; cvta.to.shared.u64 t, %1; cvt.u32.u64 %0, t; }"
        : "=r"(a) : "l"(p));
    return a;
}

__device__ __forceinline__ void ldsm_x4(uint32_t* r, uint32_t addr) {
    asm volatile("ldmatrix.sync.aligned.m8n8.x4.shared.b16 {%0,%1,%2,%3}, [%4];"
        : "=r"(r[0]), "=r"(r[1]), "=r"(r[2]), "=r"(r[3]) : "r"(addr));
}
__device__ __forceinline__ void ldsm_x4_t(uint32_t* r, uint32_t addr) {
    asm volatile("ldmatrix.sync.aligned.m8n8.x4.trans.shared.b16 {%0,%1,%2,%3}, [%4];"
        : "=r"(r[0]), "=r"(r[1]), "=r"(r[2]), "=r"(r[3]) : "r"(addr));
}

// D += A @ B : m16n8k16, bf16 in, fp32 accum
__device__ __forceinline__ void mma16816(float* d, const uint32_t* a,
                                         const uint32_t* b) {
    asm volatile("mma.sync.aligned.m16n8k16.row.col.f32.bf16.bf16.f32 "
        "{%0,%1,%2,%3}, {%4,%5,%6,%7}, {%8,%9}, {%0,%1,%2,%3};"
        : "+f"(d[0]), "+f"(d[1]), "+f"(d[2]), "+f"(d[3])
        : "r"(a[0]), "r"(a[1]), "r"(a[2]), "r"(a[3]), "r"(b[0]), "r"(b[1]));
}

__device__ __forceinline__ uint32_t pack_bf2(float a, float b) {
    __nv_bfloat162 t = __floats2bfloat162_rn(a, b);
    return *(uint32_t*)&t;
}

// chunk-table helpers: chunks of 16 key tiles per q-tile
__device__ __forceinline__ int chunk_base(int qt) {
    if (qt < 16) return qt;
    if (qt < 32) return 16 + 2 * (qt - 16);
    if (qt < 48) return 48 + 3 * (qt - 32);
    return 96 + 4 * (qt - 48);
}

// ---------------------------------------------------------------------------
// Kernel 0: one-shot weight conversion, fp32 [k][n] -> bf16 hi/lo [o][n][k].
// Grid (64, 3), 256 threads.
// ---------------------------------------------------------------------------
__global__ __launch_bounds__(256) void convert_w(
    const float* __restrict__ Wq,
    const float* __restrict__ Wk,
    const float* __restrict__ Wv)
{
    const int n = blockIdx.x;
    const int o = blockIdx.y;
    const float* W = (o == 0) ? Wq : (o == 1) ? Wk : Wv;
    __nv_bfloat16* dh = g_wh + ((size_t)o * HD + n) * EMB;
    __nv_bfloat16* dl = g_wl + ((size_t)o * HD + n) * EMB;
    for (int k = threadIdx.x; k < EMB; k += 256) {
        float f = W[(size_t)k * HD + n];
        __nv_bfloat16 h = __float2bfloat16(f);
        dh[k] = h;
        dl[k] = __float2bfloat16(f - __bfloat162float(h));
    }
}

// ---------------------------------------------------------------------------
// Kernel 1: QKV projection via warp-level bf16 MMA with hi/lo split.
// BM=128 rows/CTA, 256 threads (8 warps x m16), grid 128. BK=64.
// B tiles are pure bf16 copies from pre-converted transposed weights.
// ---------------------------------------------------------------------------
#define BROW 144                       // bytes per smem row (64 bf16 + pad)
#define QOFF_AH 0
#define QOFF_AL (128*BROW)             // 18432
#define QOFF_B  (2*128*BROW)           // 36864; 6 tiles of 64*BROW=9216
#define BTILE   (64*BROW)
#define QKV_SMEM (QOFF_B + 6*BTILE)    // 92160

__global__ __launch_bounds__(256) void qkv_mma(const float* __restrict__ x)
{
    char* smem = hx_smem;
    const uint32_t sb = smem_u32(smem);
    const int tid  = threadIdx.x;
    const int wid  = tid >> 5;
    const int lane = tid & 31;
    const int m0   = blockIdx.x * 128;

    // ldmatrix lane address components
    const int a_row  = lane & 15;
    const int a_koff = (lane >> 4) * 8;          // bf16 elems
    const int b_q    = lane >> 3;
    const int b_r    = lane & 7;
    const int b_nloc = (b_q >> 1) * 8 + b_r;     // n within 16-wide pair
    const int b_koff = (b_q & 1) * 8;

    float acc[3][8][4] = {};

    // B-copy indices: j enumerates (tile, row, seg8)
    const __nv_bfloat16* wsrc[6] = {
        g_wh + 0 * HD * EMB, g_wl + 0 * HD * EMB,
        g_wh + 1 * HD * EMB, g_wl + 1 * HD * EMB,
        g_wh + 2 * HD * EMB, g_wl + 2 * HD * EMB };

    #pragma unroll 1
    for (int c = 0; c < 16; c++) {
        __syncthreads();   // previous chunk's LDSM reads complete

        // ---- A chunk: X[m0..+127][c*64..+63] -> hi/lo bf16 smem ----
        #pragma unroll
        for (int i = 0; i < 8; i++) {
            int j  = tid + i * 256;          // 0..2047 float4s
            int r  = j >> 4;
            int c4 = (j & 15) * 4;
            float4 v = *(const float4*)(x + (size_t)(m0 + r) * EMB + c * 64 + c4);
            __nv_bfloat16 h0 = __float2bfloat16(v.x);
            __nv_bfloat16 h1 = __float2bfloat16(v.y);
            __nv_bfloat16 h2 = __float2bfloat16(v.z);
            __nv_bfloat16 h3 = __float2bfloat16(v.w);
            __nv_bfloat162 hA = {h0, h1}, hB = {h2, h3};
            __nv_bfloat162 lA = {__float2bfloat16(v.x - __bfloat162float(h0)),
                                 __float2bfloat16(v.y - __bfloat162float(h1))};
            __nv_bfloat162 lB = {__float2bfloat16(v.z - __bfloat162float(h2)),
                                 __float2bfloat16(v.w - __bfloat162float(h3))};
            uint32_t off = (uint32_t)(r * BROW + c4 * 2);
            *(uint2*)(smem + QOFF_AH + off) =
                make_uint2(*(uint32_t*)&hA, *(uint32_t*)&hB);
            *(uint2*)(smem + QOFF_AL + off) =
                make_uint2(*(uint32_t*)&lA, *(uint32_t*)&lB);
        }

        // ---- B tiles: pure uint4 copy from g_wh/g_wl[o][n][c*64..] ----
        #pragma unroll
        for (int i = 0; i < 12; i++) {
            int j    = tid + i * 256;        // 0..3071
            int t    = j >> 9;               // tile 0..5
            int row  = (j >> 3) & 63;        // n
            int seg  = j & 7;                // 8 bf16 per uint4
            *(uint4*)(smem + QOFF_B + t * BTILE + row * BROW + seg * 16) =
                *(const uint4*)(wsrc[t] + (size_t)row * EMB + c * 64 + seg * 8);
        }
        __syncthreads();

        // ---- A fragments: 2 splits x 4 k-steps ----
        uint32_t afr[2][4][4];
        #pragma unroll
        for (int spl = 0; spl < 2; spl++)
            #pragma unroll
            for (int s = 0; s < 4; s++)
                ldsm_x4(afr[spl][s],
                        sb + (spl ? QOFF_AL : QOFF_AH) +
                        (uint32_t)((wid * 16 + a_row) * BROW +
                                   (s * 16 + a_koff) * 2));

        // ---- MMAs: Xh@Wh + Xl@Wh + Xh@Wl ----
        #pragma unroll
        for (int o = 0; o < 3; o++) {
            uint32_t bhb = sb + QOFF_B + (o * 2 + 0) * BTILE;
            uint32_t blb = sb + QOFF_B + (o * 2 + 1) * BTILE;
            #pragma unroll
            for (int s = 0; s < 4; s++) {
                #pragma unroll
                for (int p = 0; p < 4; p++) {
                    uint32_t boff = (uint32_t)((p * 16 + b_nloc) * BROW +
                                               (s * 16 + b_koff) * 2);
                    uint32_t bf[4];
                    ldsm_x4(bf, bhb + boff);
                    mma16816(acc[o][2*p],   afr[0][s], bf);
                    mma16816(acc[o][2*p+1], afr[0][s], bf + 2);
                    mma16816(acc[o][2*p],   afr[1][s], bf);
                    mma16816(acc[o][2*p+1], afr[1][s], bf + 2);
                    ldsm_x4(bf, blb + boff);
                    mma16816(acc[o][2*p],   afr[0][s], bf);
                    mma16816(acc[o][2*p+1], afr[0][s], bf + 2);
                }
            }
        }
    }

    // ---- epilogue: c-frags -> bf16 hi/lo globals ----
    __nv_bfloat16* OH[3] = {g_qh, g_kh, g_vh};
    __nv_bfloat16* OL[3] = {g_ql, g_kl, g_vl};
    const int g  = lane >> 2;
    const int tg = lane & 3;
    #pragma unroll
    for (int o = 0; o < 3; o++) {
        #pragma unroll
        for (int nt = 0; nt < 8; nt++) {
            int mrow = m0 + wid * 16 + g;
            int ncol = nt * 8 + tg * 2;
            float c0 = acc[o][nt][0], c1 = acc[o][nt][1];
            float c2 = acc[o][nt][2], c3 = acc[o][nt][3];
            __nv_bfloat162 h01 = __floats2bfloat162_rn(c0, c1);
            __nv_bfloat162 h23 = __floats2bfloat162_rn(c2, c3);
            __nv_bfloat162 l01 = __floats2bfloat162_rn(
                c0 - __bfloat162float(h01.x), c1 - __bfloat162float(h01.y));
            __nv_bfloat162 l23 = __floats2bfloat162_rn(
                c2 - __bfloat162float(h23.x), c3 - __bfloat162float(h23.y));
            *(uint32_t*)&OH[o][(size_t)mrow * HD + ncol]       = *(uint32_t*)&h01;
            *(uint32_t*)&OL[o][(size_t)mrow * HD + ncol]       = *(uint32_t*)&l01;
            *(uint32_t*)&OH[o][(size_t)(mrow + 8) * HD + ncol] = *(uint32_t*)&h23;
            *(uint32_t*)&OL[o][(size_t)(mrow + 8) * HD + ncol] = *(uint32_t*)&l23;
        }
    }
}

// ---------------------------------------------------------------------------
// Kernel 2: split-K chunked flash attention on HMMA.
// Grid (160, 4): each CTA handles <=16 key tiles of one q-tile, writes
// unnormalized partial (O, m, l) to scratch. 128 threads = 4 warps x 16 rows.
// ---------------------------------------------------------------------------
#define ABROW 144
#define ATILE (64*ABROW)          // 9216 bytes per tile array
#define ATTN_SMEM (4*ATILE)       // Kh,Kl,Vh,Vl = 36864

__global__ __launch_bounds__(128) void attn_chunk()
{
    char* smem = hx_smem;
    const uint32_t sb = smem_u32(smem);
    const int tid  = threadIdx.x;
    const int wid  = tid >> 5;
    const int lane = tid & 31;
    const int g    = lane >> 2;
    const int tg   = lane & 3;

    // big-qt chunks first (LPT)
    const int x = (NXC - 1) - (int)blockIdx.x;
    const int b = blockIdx.y;
    int qt, c;
    if (x < 16)      { qt = x;                 c = 0; }
    else if (x < 48) { qt = 16 + (x - 16) / 2; c = (x - 16) & 1; }
    else if (x < 96) { qt = 32 + (x - 48) / 3; c = (x - 48) % 3; }
    else             { qt = 48 + (x - 96) / 4; c = (x - 96) & 3; }

    const int jt0 = c * 16;
    const int jt1 = min(qt + 1, jt0 + 16);
    const int r0  = qt * 64;
    const size_t tb = (size_t)b * SEQ;

    // ldmatrix lane addressing
    const int lq  = lane >> 3, lr = lane & 7;
    const int bn  = (lq >> 1) * 8 + lr;       // non-trans B: n row
    const int bk  = (lq & 1) * 8;             //               k offset
    const int trr = (lq & 1) * 8 + lr;        // trans: source row (k)
    const int trc = (lq >> 1) * 8;            //        source col (n)

    const int row_a = r0 + wid * 16 + g;      // global rows this thread owns
    const int row_b = row_a + 8;

    // ---- Q a-frags (hi/lo), loaded once from gmem ----
    uint32_t aQh[4][4], aQl[4][4];
    #pragma unroll
    for (int ks = 0; ks < 4; ks++) {
        size_t ra = (tb + row_a) * HD + ks * 16 + 2 * tg;
        size_t rb = (tb + row_b) * HD + ks * 16 + 2 * tg;
        aQh[ks][0] = *(const uint32_t*)&g_qh[ra];
        aQh[ks][1] = *(const uint32_t*)&g_qh[rb];
        aQh[ks][2] = *(const uint32_t*)&g_qh[ra + 8];
        aQh[ks][3] = *(const uint32_t*)&g_qh[rb + 8];
        aQl[ks][0] = *(const uint32_t*)&g_ql[ra];
        aQl[ks][1] = *(const uint32_t*)&g_ql[rb];
        aQl[ks][2] = *(const uint32_t*)&g_ql[ra + 8];
        aQl[ks][3] = *(const uint32_t*)&g_ql[rb + 8];
    }

    float oacc[8][4] = {};
    float mA = -1e30f, mB = -1e30f, lA = 0.0f, lB = 0.0f;

    const __nv_bfloat16* bases[4] = {g_kh + tb * HD, g_kl + tb * HD,
                                     g_vh + tb * HD, g_vl + tb * HD};

    for (int jt = jt0; jt < jt1; jt++) {
        const int s0 = jt * 64;
        __syncthreads();
        // ---- stage Kh,Kl,Vh,Vl tiles (64x64 bf16 each) ----
        {
            const int lrow = tid >> 3, lseg = tid & 7;
            #pragma unroll
            for (int i = 0; i < 16; i++) {
                int arr = i >> 2;
                int row = (i & 3) * 16 + lrow;
                *(uint4*)(smem + arr * ATILE + row * ABROW + lseg * 16) =
                    *(const uint4*)(bases[arr] + (size_t)(s0 + row) * HD + lseg * 8);
            }
        }
        __syncthreads();

        // ---- S = Q K^T (3-term hi/lo) ----
        float sacc[8][4] = {};
        #pragma unroll
        for (int ks = 0; ks < 4; ks++) {
            #pragma unroll
            for (int np = 0; np < 4; np++) {
                uint32_t boff = (uint32_t)((np * 16 + bn) * ABROW +
                                           (ks * 16 + bk) * 2);
                uint32_t bh[4], bl[4];
                ldsm_x4(bh, sb + 0 * ATILE + boff);
                ldsm_x4(bl, sb + 1 * ATILE + boff);
                mma16816(sacc[2*np],   aQh[ks], bh);
                mma16816(sacc[2*np+1], aQh[ks], bh + 2);
                mma16816(sacc[2*np],   aQl[ks], bh);
                mma16816(sacc[2*np+1], aQl[ks], bh + 2);
                mma16816(sacc[2*np],   aQh[ks], bl);
                mma16816(sacc[2*np+1], aQh[ks], bl + 2);
            }
        }

        // ---- scale + causal mask (diag tile only) ----
        const float scale = 0.03125f;   // 1/sqrt(1024)
        if (jt == qt) {
            #pragma unroll
            for (int nt = 0; nt < 8; nt++) {
                int col = s0 + nt * 8 + 2 * tg;
                sacc[nt][0] = (col     > row_a) ? -1e30f : sacc[nt][0] * scale;
                sacc[nt][1] = (col + 1 > row_a) ? -1e30f : sacc[nt][1] * scale;
                sacc[nt][2] = (col     > row_b) ? -1e30f : sacc[nt][2] * scale;
                sacc[nt][3] = (col + 1 > row_b) ? -1e30f : sacc[nt][3] * scale;
            }
        } else {
            #pragma unroll
            for (int nt = 0; nt < 8; nt++) {
                sacc[nt][0] *= scale; sacc[nt][1] *= scale;
                sacc[nt][2] *= scale; sacc[nt][3] *= scale;
            }
        }

        // ---- online softmax ----
        float rmA = -1e30f, rmB = -1e30f;
        #pragma unroll
        for (int nt = 0; nt < 8; nt++) {
            rmA = fmaxf(rmA, fmaxf(sacc[nt][0], sacc[nt][1]));
            rmB = fmaxf(rmB, fmaxf(sacc[nt][2], sacc[nt][3]));
        }
        rmA = fmaxf(rmA, __shfl_xor_sync(0xffffffffu, rmA, 1));
        rmA = fmaxf(rmA, __shfl_xor_sync(0xffffffffu, rmA, 2));
        rmB = fmaxf(rmB, __shfl_xor_sync(0xffffffffu, rmB, 1));
        rmB = fmaxf(rmB, __shfl_xor_sync(0xffffffffu, rmB, 2));

        float mnA = fmaxf(mA, rmA), mnB = fmaxf(mB, rmB);
        float alA = __expf(mA - mnA), alB = __expf(mB - mnB);
        mA = mnA; mB = mnB;

        float rsA = 0.0f, rsB = 0.0f;
        uint32_t aPh[4][4], aPl[4][4];
        #pragma unroll
        for (int s4 = 0; s4 < 4; s4++) {
            #pragma unroll
            for (int j = 0; j < 2; j++) {
                int nt = 2 * s4 + j;
                float p0 = __expf(sacc[nt][0] - mA);
                float p1 = __expf(sacc[nt][1] - mA);
                float p2 = __expf(sacc[nt][2] - mB);
                float p3 = __expf(sacc[nt][3] - mB);
                rsA += p0 + p1; rsB += p2 + p3;
                __nv_bfloat162 h01 = __floats2bfloat162_rn(p0, p1);
                __nv_bfloat162 h23 = __floats2bfloat162_rn(p2, p3);
                aPh[s4][2*j]   = *(uint32_t*)&h01;
                aPh[s4][2*j+1] = *(uint32_t*)&h23;
                aPl[s4][2*j]   = pack_bf2(p0 - __bfloat162float(h01.x),
                                          p1 - __bfloat162float(h01.y));
                aPl[s4][2*j+1] = pack_bf2(p2 - __bfloat162float(h23.x),
                                          p3 - __bfloat162float(h23.y));
            }
        }
        rsA += __shfl_xor_sync(0xffffffffu, rsA, 1);
        rsA += __shfl_xor_sync(0xffffffffu, rsA, 2);
        rsB += __shfl_xor_sync(0xffffffffu, rsB, 1);
        rsB += __shfl_xor_sync(0xffffffffu, rsB, 2);
        lA = lA * alA + rsA;
        lB = lB * alB + rsB;

        #pragma unroll
        for (int ht = 0; ht < 8; ht++) {
            oacc[ht][0] *= alA; oacc[ht][1] *= alA;
            oacc[ht][2] *= alB; oacc[ht][3] *= alB;
        }

        // ---- O += P V (3-term hi/lo), V b-frags via ldmatrix.trans ----
        #pragma unroll
        for (int ks = 0; ks < 4; ks++) {
            #pragma unroll
            for (int hp = 0; hp < 4; hp++) {
                uint32_t taddr = sb + 2 * ATILE +
                    (uint32_t)((ks * 16 + trr) * ABROW + (hp * 16 + trc) * 2);
                uint32_t vh4[4], vl4[4];
                ldsm_x4_t(vh4, taddr);
                ldsm_x4_t(vl4, taddr + ATILE);
                mma16816(oacc[2*hp],   aPh[ks], vh4);
                mma16816(oacc[2*hp+1], aPh[ks], vh4 + 2);
                mma16816(oacc[2*hp],   aPl[ks], vh4);
                mma16816(oacc[2*hp+1], aPl[ks], vh4 + 2);
                mma16816(oacc[2*hp],   aPh[ks], vl4);
                mma16816(oacc[2*hp+1], aPh[ks], vl4 + 2);
            }
        }
    }

    // ---- store unnormalized partial (O, m, l) ----
    const int cid = b * NXC + x;
    float* po = g_po + (size_t)cid * 4096;
    const int la = wid * 16 + g;      // local row a
    #pragma unroll
    for (int ht = 0; ht < 8; ht++) {
        int col = ht * 8 + 2 * tg;
        *(float2*)&po[la * 64 + col]       = make_float2(oacc[ht][0], oacc[ht][1]);
        *(float2*)&po[(la + 8) * 64 + col] = make_float2(oacc[ht][2], oacc[ht][3]);
    }
    if (tg == 0) {
        g_pm[cid * 64 + la]     = mA;
        g_pm[cid * 64 + la + 8] = mB;
        g_pl[cid * 64 + la]     = lA;
        g_pl[cid * 64 + la + 8] = lB;
    }
}

// ---------------------------------------------------------------------------
// Kernel 3: merge partial chunks. Grid (64, 4) = (qt, b), 256 threads.
// ---------------------------------------------------------------------------
__global__ __launch_bounds__(256) void attn_merge(float* __restrict__ out)
{
    const int qt = blockIdx.x;
    const int b  = blockIdx.y;
    const int nc = qt / 16 + 1;
    const int base = chunk_base(qt);

    const int r  = threadIdx.x >> 2;
    const int q4 = threadIdx.x & 3;

    float m[4], l[4];
    float M = -1e30f;
    #pragma unroll 4
    for (int i = 0; i < nc; i++) {
        int cid = b * NXC + base + i;
        m[i] = g_pm[cid * 64 + r];
        l[i] = g_pl[cid * 64 + r];
        M = fmaxf(M, m[i]);
    }
    float denom = 0.0f;
    float w[4];
    #pragma unroll 4
    for (int i = 0; i < nc; i++) {
        w[i] = __expf(m[i] - M);
        denom += l[i] * w[i];
    }
    float inv = 1.0f / denom;

    float4 acc[4] = {};
    #pragma unroll 4
    for (int i = 0; i < nc; i++) {
        const float* po = g_po + (size_t)(b * NXC + base + i) * 4096 + r * 64 + q4 * 16;
        float wi = w[i];
        #pragma unroll
        for (int v = 0; v < 4; v++) {
            float4 t = *(const float4*)(po + v * 4);
            acc[v].x += t.x * wi; acc[v].y += t.y * wi;
            acc[v].z += t.z * wi; acc[v].w += t.w * wi;
        }
    }
    float* dst = out + ((size_t)b * SEQ + qt * 64 + r) * HD + q4 * 16;
    #pragma unroll
    for (int v = 0; v < 4; v++) {
        acc[v].x *= inv; acc[v].y *= inv; acc[v].z *= inv; acc[v].w *= inv;
        *(float4*)(dst + v * 4) = acc[v];
    }
}

// ---------------------------------------------------------------------------
extern "C" void kernel_launch(void* const* d_in, const int* in_sizes, int n_in,
                              void* d_out, int out_size)
{
    const float* x  = (const float*)d_in[0];
    const float* Wq = (const float*)d_in[1];
    const float* Wk = (const float*)d_in[2];
    const float* Wv = (const float*)d_in[3];
    float* out = (float*)d_out;

    cudaFuncSetAttribute(qkv_mma,
                         cudaFuncAttributeMaxDynamicSharedMemorySize, QKV_SMEM);

    convert_w<<<dim3(64, 3), 256>>>(Wq, Wk, Wv);
    qkv_mma<<<MTOT / 128, 256, QKV_SMEM>>>(x);
    attn_chunk<<<dim3(NXC, BATCH), 128, ATTN_SMEM>>>();
    attn_merge<<<dim3(64, BATCH), 256>>>(out);
}

// round 14
// speedup vs baseline: 1.5305x; 1.0648x over previous
#include <cuda_runtime.h>
#include <cuda_bf16.h>
#include <stdint.h>
#include <math.h>

#define BATCH 4
#define SEQ   4096
#define EMB   1024
#define HD    64
#define MTOT  (BATCH*SEQ)

// bf16 hi/lo projected Q,K,V (device globals: allocation-rule-safe)
__device__ __nv_bfloat16 g_qh[MTOT*HD];
__device__ __nv_bfloat16 g_ql[MTOT*HD];
__device__ __nv_bfloat16 g_kh[MTOT*HD];
__device__ __nv_bfloat16 g_kl[MTOT*HD];
__device__ __nv_bfloat16 g_vh[MTOT*HD];
__device__ __nv_bfloat16 g_vl[MTOT*HD];

// Pre-converted weights, TRANSPOSED: [o][n=64][k=1024], hi and lo.
__device__ __nv_bfloat16 g_wh[3*HD*EMB];
__device__ __nv_bfloat16 g_wl[3*HD*EMB];

// Split-K attention partials: 160 chunks per batch, 640 total.
#define NXC 160
#define NCHUNK (BATCH*NXC)
__device__ float g_po[NCHUNK*64*64];
__device__ float g_pm[NCHUNK*64];
__device__ float g_pl[NCHUNK*64];

// Single extern shared symbol (char) — cast per kernel.
extern __shared__ char hx_smem[];

// ---------------------------------------------------------------------------
// Helpers
// ---------------------------------------------------------------------------
__device__ __forceinline__ uint32_t smem_u32(const void* p) {
    uint32_t a;
    asm("{ .reg .u64 t; cvta.to.shared.u64 t, %1; cvt.u32.u64 %0, t; }"
        : "=r"(a) : "l"(p));
    return a;
}

__device__ __forceinline__ void ldsm_x4(uint32_t* r, uint32_t addr) {
    asm volatile("ldmatrix.sync.aligned.m8n8.x4.shared.b16 {%0,%1,%2,%3}, [%4];"
        : "=r"(r[0]), "=r"(r[1]), "=r"(r[2]), "=r"(r[3]) : "r"(addr));
}
__device__ __forceinline__ void ldsm_x4_t(uint32_t* r, uint32_t addr) {
    asm volatile("ldmatrix.sync.aligned.m8n8.x4.trans.shared.b16 {%0,%1,%2,%3}, [%4];"
        : "=r"(r[0]), "=r"(r[1]), "=r"(r[2]), "=r"(r[3]) : "r"(addr));
}

// D += A @ B : m16n8k16, bf16 in, fp32 accum
__device__ __forceinline__ void mma16816(float* d, const uint32_t* a,
                                         const uint32_t* b) {
    asm volatile("mma.sync.aligned.m16n8k16.row.col.f32.bf16.bf16.f32 "
        "{%0,%1,%2,%3}, {%4,%5,%6,%7}, {%8,%9}, {%0,%1,%2,%3};"
        : "+f"(d[0]), "+f"(d[1]), "+f"(d[2]), "+f"(d[3])
        : "r"(a[0]), "r"(a[1]), "r"(a[2]), "r"(a[3]), "r"(b[0]), "r"(b[1]));
}

__device__ __forceinline__ uint32_t pack_bf2(float a, float b) {
    __nv_bfloat162 t = __floats2bfloat162_rn(a, b);
    return *(uint32_t*)&t;
}

// chunk-table helpers: chunks of 16 key tiles per q-tile
__device__ __forceinline__ int chunk_base(int qt) {
    if (qt < 16) return qt;
    if (qt < 32) return 16 + 2 * (qt - 16);
    if (qt < 48) return 48 + 3 * (qt - 32);
    return 96 + 4 * (qt - 48);
}

// ---------------------------------------------------------------------------
// Kernel 0: one-shot weight conversion, fp32 [k][n] -> bf16 hi/lo [o][n][k].
// ---------------------------------------------------------------------------
__global__ __launch_bounds__(256) void convert_w(
    const float* __restrict__ Wq,
    const float* __restrict__ Wk,
    const float* __restrict__ Wv)
{
    const int n = blockIdx.x;
    const int o = blockIdx.y;
    const float* W = (o == 0) ? Wq : (o == 1) ? Wk : Wv;
    __nv_bfloat16* dh = g_wh + ((size_t)o * HD + n) * EMB;
    __nv_bfloat16* dl = g_wl + ((size_t)o * HD + n) * EMB;
    for (int k = threadIdx.x; k < EMB; k += 256) {
        float f = W[(size_t)k * HD + n];
        __nv_bfloat16 h = __float2bfloat16(f);
        dh[k] = h;
        dl[k] = __float2bfloat16(f - __bfloat162float(h));
    }
}

// ---------------------------------------------------------------------------
// Kernel 1: QKV projection via warp-level bf16 MMA with hi/lo split.
// BM=64 rows/CTA, 128 threads (4 warps x m16), grid 256. BK=64.
// B tiles are pure uint4 copies from pre-converted transposed weights.
// ---------------------------------------------------------------------------
#define BROW 144                       // bytes per smem row (64 bf16 + pad)
#define QOFF_AH 0
#define QOFF_AL (64*BROW)              // 9216
#define QOFF_B  (2*64*BROW)            // 18432; 6 tiles of 64*BROW=9216
#define BTILE   (64*BROW)
#define QKV_SMEM (QOFF_B + 6*BTILE)    // 73728

__global__ __launch_bounds__(128) void qkv_mma(const float* __restrict__ x)
{
    char* smem = hx_smem;
    const uint32_t sb = smem_u32(smem);
    const int tid  = threadIdx.x;
    const int wid  = tid >> 5;
    const int lane = tid & 31;
    const int m0   = blockIdx.x * 64;

    // ldmatrix lane address components
    const int a_row  = lane & 15;
    const int a_koff = (lane >> 4) * 8;          // bf16 elems
    const int b_q    = lane >> 3;
    const int b_r    = lane & 7;
    const int b_nloc = (b_q >> 1) * 8 + b_r;     // n within 16-wide pair
    const int b_koff = (b_q & 1) * 8;

    float acc[3][8][4] = {};

    const __nv_bfloat16* wsrc[6] = {
        g_wh + 0 * HD * EMB, g_wl + 0 * HD * EMB,
        g_wh + 1 * HD * EMB, g_wl + 1 * HD * EMB,
        g_wh + 2 * HD * EMB, g_wl + 2 * HD * EMB };

    #pragma unroll 1
    for (int c = 0; c < 16; c++) {
        __syncthreads();   // previous chunk's LDSM reads complete

        // ---- A chunk: X[m0..+63][c*64..+63] -> hi/lo bf16 smem ----
        #pragma unroll
        for (int i = 0; i < 8; i++) {
            int j  = tid + i * 128;          // 0..1023 float4s
            int r  = j >> 4;
            int c4 = (j & 15) * 4;
            float4 v = *(const float4*)(x + (size_t)(m0 + r) * EMB + c * 64 + c4);
            __nv_bfloat16 h0 = __float2bfloat16(v.x);
            __nv_bfloat16 h1 = __float2bfloat16(v.y);
            __nv_bfloat16 h2 = __float2bfloat16(v.z);
            __nv_bfloat16 h3 = __float2bfloat16(v.w);
            __nv_bfloat162 hA = {h0, h1}, hB = {h2, h3};
            __nv_bfloat162 lA = {__float2bfloat16(v.x - __bfloat162float(h0)),
                                 __float2bfloat16(v.y - __bfloat162float(h1))};
            __nv_bfloat162 lB = {__float2bfloat16(v.z - __bfloat162float(h2)),
                                 __float2bfloat16(v.w - __bfloat162float(h3))};
            uint32_t off = (uint32_t)(r * BROW + c4 * 2);
            *(uint2*)(smem + QOFF_AH + off) =
                make_uint2(*(uint32_t*)&hA, *(uint32_t*)&hB);
            *(uint2*)(smem + QOFF_AL + off) =
                make_uint2(*(uint32_t*)&lA, *(uint32_t*)&lB);
        }

        // ---- B tiles: pure uint4 copy from g_wh/g_wl[o][n][c*64..] ----
        #pragma unroll
        for (int i = 0; i < 24; i++) {
            int j    = tid + i * 128;        // 0..3071
            int t    = j >> 9;               // tile 0..5
            int row  = (j >> 3) & 63;        // n
            int seg  = j & 7;                // 8 bf16 per uint4
            *(uint4*)(smem + QOFF_B + t * BTILE + row * BROW + seg * 16) =
                *(const uint4*)(wsrc[t] + (size_t)row * EMB + c * 64 + seg * 8);
        }
        __syncthreads();

        // ---- A fragments: 2 splits x 4 k-steps ----
        uint32_t afr[2][4][4];
        #pragma unroll
        for (int spl = 0; spl < 2; spl++)
            #pragma unroll
            for (int s = 0; s < 4; s++)
                ldsm_x4(afr[spl][s],
                        sb + (spl ? QOFF_AL : QOFF_AH) +
                        (uint32_t)((wid * 16 + a_row) * BROW +
                                   (s * 16 + a_koff) * 2));

        // ---- MMAs: Xh@Wh + Xl@Wh + Xh@Wl ----
        #pragma unroll
        for (int o = 0; o < 3; o++) {
            uint32_t bhb = sb + QOFF_B + (o * 2 + 0) * BTILE;
            uint32_t blb = sb + QOFF_B + (o * 2 + 1) * BTILE;
            #pragma unroll
            for (int s = 0; s < 4; s++) {
                #pragma unroll
                for (int p = 0; p < 4; p++) {
                    uint32_t boff = (uint32_t)((p * 16 + b_nloc) * BROW +
                                               (s * 16 + b_koff) * 2);
                    uint32_t bf[4];
                    ldsm_x4(bf, bhb + boff);
                    mma16816(acc[o][2*p],   afr[0][s], bf);
                    mma16816(acc[o][2*p+1], afr[0][s], bf + 2);
                    mma16816(acc[o][2*p],   afr[1][s], bf);
                    mma16816(acc[o][2*p+1], afr[1][s], bf + 2);
                    ldsm_x4(bf, blb + boff);
                    mma16816(acc[o][2*p],   afr[0][s], bf);
                    mma16816(acc[o][2*p+1], afr[0][s], bf + 2);
                }
            }
        }
    }

    // ---- epilogue: c-frags -> bf16 hi/lo globals ----
    __nv_bfloat16* OH[3] = {g_qh, g_kh, g_vh};
    __nv_bfloat16* OL[3] = {g_ql, g_kl, g_vl};
    const int g  = lane >> 2;
    const int tg = lane & 3;
    #pragma unroll
    for (int o = 0; o < 3; o++) {
        #pragma unroll
        for (int nt = 0; nt < 8; nt++) {
            int mrow = m0 + wid * 16 + g;
            int ncol = nt * 8 + tg * 2;
            float c0 = acc[o][nt][0], c1 = acc[o][nt][1];
            float c2 = acc[o][nt][2], c3 = acc[o][nt][3];
            __nv_bfloat162 h01 = __floats2bfloat162_rn(c0, c1);
            __nv_bfloat162 h23 = __floats2bfloat162_rn(c2, c3);
            __nv_bfloat162 l01 = __floats2bfloat162_rn(
                c0 - __bfloat162float(h01.x), c1 - __bfloat162float(h01.y));
            __nv_bfloat162 l23 = __floats2bfloat162_rn(
                c2 - __bfloat162float(h23.x), c3 - __bfloat162float(h23.y));
            *(uint32_t*)&OH[o][(size_t)mrow * HD + ncol]       = *(uint32_t*)&h01;
            *(uint32_t*)&OL[o][(size_t)mrow * HD + ncol]       = *(uint32_t*)&l01;
            *(uint32_t*)&OH[o][(size_t)(mrow + 8) * HD + ncol] = *(uint32_t*)&h23;
            *(uint32_t*)&OL[o][(size_t)(mrow + 8) * HD + ncol] = *(uint32_t*)&l23;
        }
    }
}

// ---------------------------------------------------------------------------
// Kernel 2: split-K chunked flash attention on HMMA.
// QK^T uses 2-term hi/lo (QhKh + QlKh); PV uses 3 terms. Kl never staged.
// Grid (160, 4), 128 threads = 4 warps x 16 rows.
// ---------------------------------------------------------------------------
#define ABROW 144
#define ATILE (64*ABROW)          // 9216 bytes per tile array
#define ATTN_SMEM (3*ATILE)       // Kh,Vh,Vl = 27648

__global__ __launch_bounds__(128) void attn_chunk()
{
    char* smem = hx_smem;
    const uint32_t sb = smem_u32(smem);
    const int tid  = threadIdx.x;
    const int wid  = tid >> 5;
    const int lane = tid & 31;
    const int g    = lane >> 2;
    const int tg   = lane & 3;

    // big-qt chunks first (LPT)
    const int x = (NXC - 1) - (int)blockIdx.x;
    const int b = blockIdx.y;
    int qt, c;
    if (x < 16)      { qt = x;                 c = 0; }
    else if (x < 48) { qt = 16 + (x - 16) / 2; c = (x - 16) & 1; }
    else if (x < 96) { qt = 32 + (x - 48) / 3; c = (x - 48) % 3; }
    else             { qt = 48 + (x - 96) / 4; c = (x - 96) & 3; }

    const int jt0 = c * 16;
    const int jt1 = min(qt + 1, jt0 + 16);
    const int r0  = qt * 64;
    const size_t tb = (size_t)b * SEQ;

    // ldmatrix lane addressing
    const int lq  = lane >> 3, lr = lane & 7;
    const int bn  = (lq >> 1) * 8 + lr;       // non-trans B: n row
    const int bk  = (lq & 1) * 8;             //               k offset
    const int trr = (lq & 1) * 8 + lr;        // trans: source row (k)
    const int trc = (lq >> 1) * 8;            //        source col (n)

    const int row_a = r0 + wid * 16 + g;      // global rows this thread owns
    const int row_b = row_a + 8;

    // ---- Q a-frags (hi/lo), loaded once from gmem ----
    uint32_t aQh[4][4], aQl[4][4];
    #pragma unroll
    for (int ks = 0; ks < 4; ks++) {
        size_t ra = (tb + row_a) * HD + ks * 16 + 2 * tg;
        size_t rb = (tb + row_b) * HD + ks * 16 + 2 * tg;
        aQh[ks][0] = *(const uint32_t*)&g_qh[ra];
        aQh[ks][1] = *(const uint32_t*)&g_qh[rb];
        aQh[ks][2] = *(const uint32_t*)&g_qh[ra + 8];
        aQh[ks][3] = *(const uint32_t*)&g_qh[rb + 8];
        aQl[ks][0] = *(const uint32_t*)&g_ql[ra];
        aQl[ks][1] = *(const uint32_t*)&g_ql[rb];
        aQl[ks][2] = *(const uint32_t*)&g_ql[ra + 8];
        aQl[ks][3] = *(const uint32_t*)&g_ql[rb + 8];
    }

    float oacc[8][4] = {};
    float mA = -1e30f, mB = -1e30f, lA = 0.0f, lB = 0.0f;

    const __nv_bfloat16* bases[3] = {g_kh + tb * HD, g_vh + tb * HD,
                                     g_vl + tb * HD};

    for (int jt = jt0; jt < jt1; jt++) {
        const int s0 = jt * 64;
        __syncthreads();
        // ---- stage Kh,Vh,Vl tiles (64x64 bf16 each) ----
        {
            const int lrow = tid >> 3, lseg = tid & 7;
            #pragma unroll
            for (int i = 0; i < 12; i++) {
                int arr = i >> 2;
                int row = (i & 3) * 16 + lrow;
                *(uint4*)(smem + arr * ATILE + row * ABROW + lseg * 16) =
                    *(const uint4*)(bases[arr] + (size_t)(s0 + row) * HD + lseg * 8);
            }
        }
        __syncthreads();

        // ---- S = Q K^T (2-term hi/lo: QhKh + QlKh) ----
        float sacc[8][4] = {};
        #pragma unroll
        for (int ks = 0; ks < 4; ks++) {
            #pragma unroll
            for (int np = 0; np < 4; np++) {
                uint32_t boff = (uint32_t)((np * 16 + bn) * ABROW +
                                           (ks * 16 + bk) * 2);
                uint32_t bh[4];
                ldsm_x4(bh, sb + boff);
                mma16816(sacc[2*np],   aQh[ks], bh);
                mma16816(sacc[2*np+1], aQh[ks], bh + 2);
                mma16816(sacc[2*np],   aQl[ks], bh);
                mma16816(sacc[2*np+1], aQl[ks], bh + 2);
            }
        }

        // ---- scale + causal mask (diag tile only) ----
        const float scale = 0.03125f;   // 1/sqrt(1024)
        if (jt == qt) {
            #pragma unroll
            for (int nt = 0; nt < 8; nt++) {
                int col = s0 + nt * 8 + 2 * tg;
                sacc[nt][0] = (col     > row_a) ? -1e30f : sacc[nt][0] * scale;
                sacc[nt][1] = (col + 1 > row_a) ? -1e30f : sacc[nt][1] * scale;
                sacc[nt][2] = (col     > row_b) ? -1e30f : sacc[nt][2] * scale;
                sacc[nt][3] = (col + 1 > row_b) ? -1e30f : sacc[nt][3] * scale;
            }
        } else {
            #pragma unroll
            for (int nt = 0; nt < 8; nt++) {
                sacc[nt][0] *= scale; sacc[nt][1] *= scale;
                sacc[nt][2] *= scale; sacc[nt][3] *= scale;
            }
        }

        // ---- online softmax ----
        float rmA = -1e30f, rmB = -1e30f;
        #pragma unroll
        for (int nt = 0; nt < 8; nt++) {
            rmA = fmaxf(rmA, fmaxf(sacc[nt][0], sacc[nt][1]));
            rmB = fmaxf(rmB, fmaxf(sacc[nt][2], sacc[nt][3]));
        }
        rmA = fmaxf(rmA, __shfl_xor_sync(0xffffffffu, rmA, 1));
        rmA = fmaxf(rmA, __shfl_xor_sync(0xffffffffu, rmA, 2));
        rmB = fmaxf(rmB, __shfl_xor_sync(0xffffffffu, rmB, 1));
        rmB = fmaxf(rmB, __shfl_xor_sync(0xffffffffu, rmB, 2));

        float mnA = fmaxf(mA, rmA), mnB = fmaxf(mB, rmB);
        float alA = __expf(mA - mnA), alB = __expf(mB - mnB);
        mA = mnA; mB = mnB;

        float rsA = 0.0f, rsB = 0.0f;
        uint32_t aPh[4][4], aPl[4][4];
        #pragma unroll
        for (int s4 = 0; s4 < 4; s4++) {
            #pragma unroll
            for (int j = 0; j < 2; j++) {
                int nt = 2 * s4 + j;
                float p0 = __expf(sacc[nt][0] - mA);
                float p1 = __expf(sacc[nt][1] - mA);
                float p2 = __expf(sacc[nt][2] - mB);
                float p3 = __expf(sacc[nt][3] - mB);
                rsA += p0 + p1; rsB += p2 + p3;
                __nv_bfloat162 h01 = __floats2bfloat162_rn(p0, p1);
                __nv_bfloat162 h23 = __floats2bfloat162_rn(p2, p3);
                aPh[s4][2*j]   = *(uint32_t*)&h01;
                aPh[s4][2*j+1] = *(uint32_t*)&h23;
                aPl[s4][2*j]   = pack_bf2(p0 - __bfloat162float(h01.x),
                                          p1 - __bfloat162float(h01.y));
                aPl[s4][2*j+1] = pack_bf2(p2 - __bfloat162float(h23.x),
                                          p3 - __bfloat162float(h23.y));
            }
        }
        rsA += __shfl_xor_sync(0xffffffffu, rsA, 1);
        rsA += __shfl_xor_sync(0xffffffffu, rsA, 2);
        rsB += __shfl_xor_sync(0xffffffffu, rsB, 1);
        rsB += __shfl_xor_sync(0xffffffffu, rsB, 2);
        lA = lA * alA + rsA;
        lB = lB * alB + rsB;

        #pragma unroll
        for (int ht = 0; ht < 8; ht++) {
            oacc[ht][0] *= alA; oacc[ht][1] *= alA;
            oacc[ht][2] *= alB; oacc[ht][3] *= alB;
        }

        // ---- O += P V (3-term hi/lo), V b-frags via ldmatrix.trans ----
        #pragma unroll
        for (int ks = 0; ks < 4; ks++) {
            #pragma unroll
            for (int hp = 0; hp < 4; hp++) {
                uint32_t taddr = sb + 1 * ATILE +
                    (uint32_t)((ks * 16 + trr) * ABROW + (hp * 16 + trc) * 2);
                uint32_t vh4[4], vl4[4];
                ldsm_x4_t(vh4, taddr);
                ldsm_x4_t(vl4, taddr + ATILE);
                mma16816(oacc[2*hp],   aPh[ks], vh4);
                mma16816(oacc[2*hp+1], aPh[ks], vh4 + 2);
                mma16816(oacc[2*hp],   aPl[ks], vh4);
                mma16816(oacc[2*hp+1], aPl[ks], vh4 + 2);
                mma16816(oacc[2*hp],   aPh[ks], vl4);
                mma16816(oacc[2*hp+1], aPh[ks], vl4 + 2);
            }
        }
    }

    // ---- store unnormalized partial (O, m, l) ----
    const int cid = b * NXC + x;
    float* po = g_po + (size_t)cid * 4096;
    const int la = wid * 16 + g;      // local row a
    #pragma unroll
    for (int ht = 0; ht < 8; ht++) {
        int col = ht * 8 + 2 * tg;
        *(float2*)&po[la * 64 + col]       = make_float2(oacc[ht][0], oacc[ht][1]);
        *(float2*)&po[(la + 8) * 64 + col] = make_float2(oacc[ht][2], oacc[ht][3]);
    }
    if (tg == 0) {
        g_pm[cid * 64 + la]     = mA;
        g_pm[cid * 64 + la + 8] = mB;
        g_pl[cid * 64 + la]     = lA;
        g_pl[cid * 64 + la + 8] = lB;
    }
}

// ---------------------------------------------------------------------------
// Kernel 3: merge partial chunks. Grid (64, 4) = (qt, b), 256 threads.
// ---------------------------------------------------------------------------
__global__ __launch_bounds__(256) void attn_merge(float* __restrict__ out)
{
    const int qt = blockIdx.x;
    const int b  = blockIdx.y;
    const int nc = qt / 16 + 1;
    const int base = chunk_base(qt);

    const int r  = threadIdx.x >> 2;
    const int q4 = threadIdx.x & 3;

    float m[4], l[4];
    float M = -1e30f;
    #pragma unroll 4
    for (int i = 0; i < nc; i++) {
        int cid = b * NXC + base + i;
        m[i] = g_pm[cid * 64 + r];
        l[i] = g_pl[cid * 64 + r];
        M = fmaxf(M, m[i]);
    }
    float denom = 0.0f;
    float w[4];
    #pragma unroll 4
    for (int i = 0; i < nc; i++) {
        w[i] = __expf(m[i] - M);
        denom += l[i] * w[i];
    }
    float inv = 1.0f / denom;

    float4 acc[4] = {};
    #pragma unroll 4
    for (int i = 0; i < nc; i++) {
        const float* po = g_po + (size_t)(b * NXC + base + i) * 4096 + r * 64 + q4 * 16;
        float wi = w[i];
        #pragma unroll
        for (int v = 0; v < 4; v++) {
            float4 t = *(const float4*)(po + v * 4);
            acc[v].x += t.x * wi; acc[v].y += t.y * wi;
            acc[v].z += t.z * wi; acc[v].w += t.w * wi;
        }
    }
    float* dst = out + ((size_t)b * SEQ + qt * 64 + r) * HD + q4 * 16;
    #pragma unroll
    for (int v = 0; v < 4; v++) {
        acc[v].x *= inv; acc[v].y *= inv; acc[v].z *= inv; acc[v].w *= inv;
        *(float4*)(dst + v * 4) = acc[v];
    }
}

// ---------------------------------------------------------------------------
extern "C" void kernel_launch(void* const* d_in, const int* in_sizes, int n_in,
                              void* d_out, int out_size)
{
    const float* x  = (const float*)d_in[0];
    const float* Wq = (const float*)d_in[1];
    const float* Wk = (const float*)d_in[2];
    const float* Wv = (const float*)d_in[3];
    float* out = (float*)d_out;

    cudaFuncSetAttribute(qkv_mma,
                         cudaFuncAttributeMaxDynamicSharedMemorySize, QKV_SMEM);

    convert_w<<<dim3(64, 3), 256>>>(Wq, Wk, Wv);
    qkv_mma<<<MTOT / 64, 128, QKV_SMEM>>>(x);
    attn_chunk<<<dim3(NXC, BATCH), 128, ATTN_SMEM>>>();
    attn_merge<<<dim3(64, BATCH), 256>>>(out);
}

// round 16
// speedup vs baseline: 1.7213x; 1.1247x over previous
#include <cuda_runtime.h>
#include <cuda_fp16.h>
#include <stdint.h>
#include <math.h>

#define BATCH 4
#define SEQ   4096
#define EMB   1024
#define HD    64
#define MTOT  (BATCH*SEQ)

// fp16 projected q,k (single) and v (hi/lo) — device globals
__device__ __half g_q [MTOT*HD];
__device__ __half g_k [MTOT*HD];
__device__ __half g_vh[MTOT*HD];
__device__ __half g_vl[MTOT*HD];

// Pre-converted weights, TRANSPOSED: [o][n=64][k=1024], hi and lo (fp16).
__device__ __half g_wh[3*HD*EMB];
__device__ __half g_wl[3*HD*EMB];

// Split-K attention partials: 160 chunks per batch, 640 total.
#define NXC 160
#define NCHUNK (BATCH*NXC)
__device__ float g_po[NCHUNK*64*64];
__device__ float g_pm[NCHUNK*64];
__device__ float g_pl[NCHUNK*64];

// Single extern shared symbol (char) — cast per kernel.
extern __shared__ char hx_smem[];

// ---------------------------------------------------------------------------
// Helpers
// ---------------------------------------------------------------------------
__device__ __forceinline__ uint32_t smem_u32(const void* p) {
    uint32_t a;
    asm("{ .reg .u64 t; cvta.to.shared.u64 t, %1; cvt.u32.u64 %0, t; }"
        : "=r"(a) : "l"(p));
    return a;
}

__device__ __forceinline__ void ldsm_x4(uint32_t* r, uint32_t addr) {
    asm volatile("ldmatrix.sync.aligned.m8n8.x4.shared.b16 {%0,%1,%2,%3}, [%4];"
        : "=r"(r[0]), "=r"(r[1]), "=r"(r[2]), "=r"(r[3]) : "r"(addr));
}
__device__ __forceinline__ void ldsm_x4_t(uint32_t* r, uint32_t addr) {
    asm volatile("ldmatrix.sync.aligned.m8n8.x4.trans.shared.b16 {%0,%1,%2,%3}, [%4];"
        : "=r"(r[0]), "=r"(r[1]), "=r"(r[2]), "=r"(r[3]) : "r"(addr));
}

// D += A @ B : m16n8k16, fp16 in, fp32 accum
__device__ __forceinline__ void mma16816(float* d, const uint32_t* a,
                                         const uint32_t* b) {
    asm volatile("mma.sync.aligned.m16n8k16.row.col.f32.f16.f16.f32 "
        "{%0,%1,%2,%3}, {%4,%5,%6,%7}, {%8,%9}, {%0,%1,%2,%3};"
        : "+f"(d[0]), "+f"(d[1]), "+f"(d[2]), "+f"(d[3])
        : "r"(a[0]), "r"(a[1]), "r"(a[2]), "r"(a[3]), "r"(b[0]), "r"(b[1]));
}

__device__ __forceinline__ uint32_t pack_h2(float a, float b) {
    __half2 t = __floats2half2_rn(a, b);
    return *(uint32_t*)&t;
}

// chunk-table helpers: chunks of 16 key tiles per q-tile
__device__ __forceinline__ int chunk_base(int qt) {
    if (qt < 16) return qt;
    if (qt < 32) return 16 + 2 * (qt - 16);
    if (qt < 48) return 48 + 3 * (qt - 32);
    return 96 + 4 * (qt - 48);
}

// ---------------------------------------------------------------------------
// Kernel 0: one-shot weight conversion, fp32 [k][n] -> fp16 hi/lo [o][n][k].
// ---------------------------------------------------------------------------
__global__ __launch_bounds__(256) void convert_w(
    const float* __restrict__ Wq,
    const float* __restrict__ Wk,
    const float* __restrict__ Wv)
{
    const int n = blockIdx.x;
    const int o = blockIdx.y;
    const float* W = (o == 0) ? Wq : (o == 1) ? Wk : Wv;
    __half* dh = g_wh + ((size_t)o * HD + n) * EMB;
    __half* dl = g_wl + ((size_t)o * HD + n) * EMB;
    for (int k = threadIdx.x; k < EMB; k += 256) {
        float f = W[(size_t)k * HD + n];
        __half h = __float2half_rn(f);
        dh[k] = h;
        dl[k] = __float2half_rn(f - __half2float(h));
    }
}

// ---------------------------------------------------------------------------
// Kernel 1: QKV projection via warp-level fp16 MMA with hi/lo split (3-term).
// BM=64 rows/CTA, 128 threads (4 warps x m16), grid 256. BK=64.
// ---------------------------------------------------------------------------
#define BROW 144                       // bytes per smem row (64 fp16 + pad)
#define QOFF_AH 0
#define QOFF_AL (64*BROW)              // 9216
#define QOFF_B  (2*64*BROW)            // 18432; 6 tiles of 64*BROW=9216
#define BTILE   (64*BROW)
#define QKV_SMEM (QOFF_B + 6*BTILE)    // 73728

__global__ __launch_bounds__(128) void qkv_mma(const float* __restrict__ x)
{
    char* smem = hx_smem;
    const uint32_t sb = smem_u32(smem);
    const int tid  = threadIdx.x;
    const int wid  = tid >> 5;
    const int lane = tid & 31;
    const int m0   = blockIdx.x * 64;

    // ldmatrix lane address components
    const int a_row  = lane & 15;
    const int a_koff = (lane >> 4) * 8;          // fp16 elems
    const int b_q    = lane >> 3;
    const int b_r    = lane & 7;
    const int b_nloc = (b_q >> 1) * 8 + b_r;     // n within 16-wide pair
    const int b_koff = (b_q & 1) * 8;

    float acc[3][8][4] = {};

    const __half* wsrc[6] = {
        g_wh + 0 * HD * EMB, g_wl + 0 * HD * EMB,
        g_wh + 1 * HD * EMB, g_wl + 1 * HD * EMB,
        g_wh + 2 * HD * EMB, g_wl + 2 * HD * EMB };

    #pragma unroll 1
    for (int c = 0; c < 16; c++) {
        __syncthreads();   // previous chunk's LDSM reads complete

        // ---- A chunk: X[m0..+63][c*64..+63] -> hi/lo fp16 smem ----
        #pragma unroll
        for (int i = 0; i < 8; i++) {
            int j  = tid + i * 128;          // 0..1023 float4s
            int r  = j >> 4;
            int c4 = (j & 15) * 4;
            float4 v = *(const float4*)(x + (size_t)(m0 + r) * EMB + c * 64 + c4);
            __half h0 = __float2half_rn(v.x);
            __half h1 = __float2half_rn(v.y);
            __half h2 = __float2half_rn(v.z);
            __half h3 = __float2half_rn(v.w);
            __half2 hA = {h0, h1}, hB = {h2, h3};
            __half2 lA = {__float2half_rn(v.x - __half2float(h0)),
                          __float2half_rn(v.y - __half2float(h1))};
            __half2 lB = {__float2half_rn(v.z - __half2float(h2)),
                          __float2half_rn(v.w - __half2float(h3))};
            uint32_t off = (uint32_t)(r * BROW + c4 * 2);
            *(uint2*)(smem + QOFF_AH + off) =
                make_uint2(*(uint32_t*)&hA, *(uint32_t*)&hB);
            *(uint2*)(smem + QOFF_AL + off) =
                make_uint2(*(uint32_t*)&lA, *(uint32_t*)&lB);
        }

        // ---- B tiles: pure uint4 copy from g_wh/g_wl[o][n][c*64..] ----
        #pragma unroll
        for (int i = 0; i < 24; i++) {
            int j    = tid + i * 128;        // 0..3071
            int t    = j >> 9;               // tile 0..5
            int row  = (j >> 3) & 63;        // n
            int seg  = j & 7;                // 8 fp16 per uint4
            *(uint4*)(smem + QOFF_B + t * BTILE + row * BROW + seg * 16) =
                *(const uint4*)(wsrc[t] + (size_t)row * EMB + c * 64 + seg * 8);
        }
        __syncthreads();

        // ---- A fragments: 2 splits x 4 k-steps ----
        uint32_t afr[2][4][4];
        #pragma unroll
        for (int spl = 0; spl < 2; spl++)
            #pragma unroll
            for (int s = 0; s < 4; s++)
                ldsm_x4(afr[spl][s],
                        sb + (spl ? QOFF_AL : QOFF_AH) +
                        (uint32_t)((wid * 16 + a_row) * BROW +
                                   (s * 16 + a_koff) * 2));

        // ---- MMAs: Xh@Wh + Xl@Wh + Xh@Wl ----
        #pragma unroll
        for (int o = 0; o < 3; o++) {
            uint32_t bhb = sb + QOFF_B + (o * 2 + 0) * BTILE;
            uint32_t blb = sb + QOFF_B + (o * 2 + 1) * BTILE;
            #pragma unroll
            for (int s = 0; s < 4; s++) {
                #pragma unroll
                for (int p = 0; p < 4; p++) {
                    uint32_t boff = (uint32_t)((p * 16 + b_nloc) * BROW +
                                               (s * 16 + b_koff) * 2);
                    uint32_t bf[4];
                    ldsm_x4(bf, bhb + boff);
                    mma16816(acc[o][2*p],   afr[0][s], bf);
                    mma16816(acc[o][2*p+1], afr[0][s], bf + 2);
                    mma16816(acc[o][2*p],   afr[1][s], bf);
                    mma16816(acc[o][2*p+1], afr[1][s], bf + 2);
                    ldsm_x4(bf, blb + boff);
                    mma16816(acc[o][2*p],   afr[0][s], bf);
                    mma16816(acc[o][2*p+1], afr[0][s], bf + 2);
                }
            }
        }
    }

    // ---- epilogue: q,k -> single fp16; v -> fp16 hi/lo ----
    const int g  = lane >> 2;
    const int tg = lane & 3;
    #pragma unroll
    for (int o = 0; o < 3; o++) {
        #pragma unroll
        for (int nt = 0; nt < 8; nt++) {
            int mrow = m0 + wid * 16 + g;
            int ncol = nt * 8 + tg * 2;
            float c0 = acc[o][nt][0], c1 = acc[o][nt][1];
            float c2 = acc[o][nt][2], c3 = acc[o][nt][3];
            __half2 h01 = __floats2half2_rn(c0, c1);
            __half2 h23 = __floats2half2_rn(c2, c3);
            if (o < 2) {
                __half* dst = (o == 0) ? g_q : g_k;
                *(uint32_t*)&dst[(size_t)mrow * HD + ncol]       = *(uint32_t*)&h01;
                *(uint32_t*)&dst[(size_t)(mrow + 8) * HD + ncol] = *(uint32_t*)&h23;
            } else {
                __half2 l01 = __floats2half2_rn(
                    c0 - __half2float(h01.x), c1 - __half2float(h01.y));
                __half2 l23 = __floats2half2_rn(
                    c2 - __half2float(h23.x), c3 - __half2float(h23.y));
                *(uint32_t*)&g_vh[(size_t)mrow * HD + ncol]       = *(uint32_t*)&h01;
                *(uint32_t*)&g_vl[(size_t)mrow * HD + ncol]       = *(uint32_t*)&l01;
                *(uint32_t*)&g_vh[(size_t)(mrow + 8) * HD + ncol] = *(uint32_t*)&h23;
                *(uint32_t*)&g_vl[(size_t)(mrow + 8) * HD + ncol] = *(uint32_t*)&l23;
            }
        }
    }
}

// ---------------------------------------------------------------------------
// Kernel 2: split-K chunked flash attention on fp16 HMMA.
// QK^T: 1 term (fp16 q,k). PV: 3 terms (PhVh + PlVh + PhVl).
// Grid (160, 4), 128 threads = 4 warps x 16 rows.
// ---------------------------------------------------------------------------
#define ABROW 144
#define ATILE (64*ABROW)          // 9216 bytes per tile array
#define ATTN_SMEM (3*ATILE)       // K,Vh,Vl = 27648

__global__ __launch_bounds__(128) void attn_chunk()
{
    char* smem = hx_smem;
    const uint32_t sb = smem_u32(smem);
    const int tid  = threadIdx.x;
    const int wid  = tid >> 5;
    const int lane = tid & 31;
    const int g    = lane >> 2;
    const int tg   = lane & 3;

    // big-qt chunks first (LPT)
    const int x = (NXC - 1) - (int)blockIdx.x;
    const int b = blockIdx.y;
    int qt, c;
    if (x < 16)      { qt = x;                 c = 0; }
    else if (x < 48) { qt = 16 + (x - 16) / 2; c = (x - 16) & 1; }
    else if (x < 96) { qt = 32 + (x - 48) / 3; c = (x - 48) % 3; }
    else             { qt = 48 + (x - 96) / 4; c = (x - 96) & 3; }

    const int jt0 = c * 16;
    const int jt1 = min(qt + 1, jt0 + 16);
    const int r0  = qt * 64;
    const size_t tb = (size_t)b * SEQ;

    // ldmatrix lane addressing
    const int lq  = lane >> 3, lr = lane & 7;
    const int bn  = (lq >> 1) * 8 + lr;       // non-trans B: n row
    const int bk  = (lq & 1) * 8;             //               k offset
    const int trr = (lq & 1) * 8 + lr;        // trans: source row (k)
    const int trc = (lq >> 1) * 8;            //        source col (n)

    const int row_a = r0 + wid * 16 + g;      // global rows this thread owns
    const int row_b = row_a + 8;

    // ---- Q a-frags (single fp16), loaded once from gmem ----
    uint32_t aQ[4][4];
    #pragma unroll
    for (int ks = 0; ks < 4; ks++) {
        size_t ra = (tb + row_a) * HD + ks * 16 + 2 * tg;
        size_t rb = (tb + row_b) * HD + ks * 16 + 2 * tg;
        aQ[ks][0] = *(const uint32_t*)&g_q[ra];
        aQ[ks][1] = *(const uint32_t*)&g_q[rb];
        aQ[ks][2] = *(const uint32_t*)&g_q[ra + 8];
        aQ[ks][3] = *(const uint32_t*)&g_q[rb + 8];
    }

    float oacc[8][4] = {};
    float mA = -1e30f, mB = -1e30f, lA = 0.0f, lB = 0.0f;

    const __half* bases[3] = {g_k + tb * HD, g_vh + tb * HD, g_vl + tb * HD};

    for (int jt = jt0; jt < jt1; jt++) {
        const int s0 = jt * 64;
        __syncthreads();
        // ---- stage K,Vh,Vl tiles (64x64 fp16 each) ----
        {
            const int lrow = tid >> 3, lseg = tid & 7;
            #pragma unroll
            for (int i = 0; i < 12; i++) {
                int arr = i >> 2;
                int row = (i & 3) * 16 + lrow;
                *(uint4*)(smem + arr * ATILE + row * ABROW + lseg * 16) =
                    *(const uint4*)(bases[arr] + (size_t)(s0 + row) * HD + lseg * 8);
            }
        }
        __syncthreads();

        // ---- S = Q K^T (1 term, fp16) ----
        float sacc[8][4] = {};
        #pragma unroll
        for (int ks = 0; ks < 4; ks++) {
            #pragma unroll
            for (int np = 0; np < 4; np++) {
                uint32_t boff = (uint32_t)((np * 16 + bn) * ABROW +
                                           (ks * 16 + bk) * 2);
                uint32_t bh[4];
                ldsm_x4(bh, sb + boff);
                mma16816(sacc[2*np],   aQ[ks], bh);
                mma16816(sacc[2*np+1], aQ[ks], bh + 2);
            }
        }

        // ---- scale + causal mask (diag tile only) ----
        const float scale = 0.03125f;   // 1/sqrt(1024)
        if (jt == qt) {
            #pragma unroll
            for (int nt = 0; nt < 8; nt++) {
                int col = s0 + nt * 8 + 2 * tg;
                sacc[nt][0] = (col     > row_a) ? -1e30f : sacc[nt][0] * scale;
                sacc[nt][1] = (col + 1 > row_a) ? -1e30f : sacc[nt][1] * scale;
                sacc[nt][2] = (col     > row_b) ? -1e30f : sacc[nt][2] * scale;
                sacc[nt][3] = (col + 1 > row_b) ? -1e30f : sacc[nt][3] * scale;
            }
        } else {
            #pragma unroll
            for (int nt = 0; nt < 8; nt++) {
                sacc[nt][0] *= scale; sacc[nt][1] *= scale;
                sacc[nt][2] *= scale; sacc[nt][3] *= scale;
            }
        }

        // ---- online softmax ----
        float rmA = -1e30f, rmB = -1e30f;
        #pragma unroll
        for (int nt = 0; nt < 8; nt++) {
            rmA = fmaxf(rmA, fmaxf(sacc[nt][0], sacc[nt][1]));
            rmB = fmaxf(rmB, fmaxf(sacc[nt][2], sacc[nt][3]));
        }
        rmA = fmaxf(rmA, __shfl_xor_sync(0xffffffffu, rmA, 1));
        rmA = fmaxf(rmA, __shfl_xor_sync(0xffffffffu, rmA, 2));
        rmB = fmaxf(rmB, __shfl_xor_sync(0xffffffffu, rmB, 1));
        rmB = fmaxf(rmB, __shfl_xor_sync(0xffffffffu, rmB, 2));

        float mnA = fmaxf(mA, rmA), mnB = fmaxf(mB, rmB);
        float alA = __expf(mA - mnA), alB = __expf(mB - mnB);
        mA = mnA; mB = mnB;

        float rsA = 0.0f, rsB = 0.0f;
        uint32_t aPh[4][4], aPl[4][4];
        #pragma unroll
        for (int s4 = 0; s4 < 4; s4++) {
            #pragma unroll
            for (int j = 0; j < 2; j++) {
                int nt = 2 * s4 + j;
                float p0 = __expf(sacc[nt][0] - mA);
                float p1 = __expf(sacc[nt][1] - mA);
                float p2 = __expf(sacc[nt][2] - mB);
                float p3 = __expf(sacc[nt][3] - mB);
                rsA += p0 + p1; rsB += p2 + p3;
                __half2 h01 = __floats2half2_rn(p0, p1);
                __half2 h23 = __floats2half2_rn(p2, p3);
                aPh[s4][2*j]   = *(uint32_t*)&h01;
                aPh[s4][2*j+1] = *(uint32_t*)&h23;
                aPl[s4][2*j]   = pack_h2(p0 - __half2float(h01.x),
                                         p1 - __half2float(h01.y));
                aPl[s4][2*j+1] = pack_h2(p2 - __half2float(h23.x),
                                         p3 - __half2float(h23.y));
            }
        }
        rsA += __shfl_xor_sync(0xffffffffu, rsA, 1);
        rsA += __shfl_xor_sync(0xffffffffu, rsA, 2);
        rsB += __shfl_xor_sync(0xffffffffu, rsB, 1);
        rsB += __shfl_xor_sync(0xffffffffu, rsB, 2);
        lA = lA * alA + rsA;
        lB = lB * alB + rsB;

        #pragma unroll
        for (int ht = 0; ht < 8; ht++) {
            oacc[ht][0] *= alA; oacc[ht][1] *= alA;
            oacc[ht][2] *= alB; oacc[ht][3] *= alB;
        }

        // ---- O += P V (3-term hi/lo), V b-frags via ldmatrix.trans ----
        #pragma unroll
        for (int ks = 0; ks < 4; ks++) {
            #pragma unroll
            for (int hp = 0; hp < 4; hp++) {
                uint32_t taddr = sb + 1 * ATILE +
                    (uint32_t)((ks * 16 + trr) * ABROW + (hp * 16 + trc) * 2);
                uint32_t vh4[4], vl4[4];
                ldsm_x4_t(vh4, taddr);
                ldsm_x4_t(vl4, taddr + ATILE);
                mma16816(oacc[2*hp],   aPh[ks], vh4);
                mma16816(oacc[2*hp+1], aPh[ks], vh4 + 2);
                mma16816(oacc[2*hp],   aPl[ks], vh4);
                mma16816(oacc[2*hp+1], aPl[ks], vh4 + 2);
                mma16816(oacc[2*hp],   aPh[ks], vl4);
                mma16816(oacc[2*hp+1], aPh[ks], vl4 + 2);
            }
        }
    }

    // ---- store unnormalized partial (O, m, l) ----
    const int cid = b * NXC + x;
    float* po = g_po + (size_t)cid * 4096;
    const int la = wid * 16 + g;      // local row a
    #pragma unroll
    for (int ht = 0; ht < 8; ht++) {
        int col = ht * 8 + 2 * tg;
        *(float2*)&po[la * 64 + col]       = make_float2(oacc[ht][0], oacc[ht][1]);
        *(float2*)&po[(la + 8) * 64 + col] = make_float2(oacc[ht][2], oacc[ht][3]);
    }
    if (tg == 0) {
        g_pm[cid * 64 + la]     = mA;
        g_pm[cid * 64 + la + 8] = mB;
        g_pl[cid * 64 + la]     = lA;
        g_pl[cid * 64 + la + 8] = lB;
    }
}

// ---------------------------------------------------------------------------
// Kernel 3: merge partial chunks. Grid (64, 4) = (qt, b), 256 threads.
// ---------------------------------------------------------------------------
__global__ __launch_bounds__(256) void attn_merge(float* __restrict__ out)
{
    const int qt = blockIdx.x;
    const int b  = blockIdx.y;
    const int nc = qt / 16 + 1;
    const int base = chunk_base(qt);

    const int r  = threadIdx.x >> 2;
    const int q4 = threadIdx.x & 3;

    float m[4], l[4];
    float M = -1e30f;
    #pragma unroll 4
    for (int i = 0; i < nc; i++) {
        int cid = b * NXC + base + i;
        m[i] = g_pm[cid * 64 + r];
        l[i] = g_pl[cid * 64 + r];
        M = fmaxf(M, m[i]);
    }
    float denom = 0.0f;
    float w[4];
    #pragma unroll 4
    for (int i = 0; i < nc; i++) {
        w[i] = __expf(m[i] - M);
        denom += l[i] * w[i];
    }
    float inv = 1.0f / denom;

    float4 acc[4] = {};
    #pragma unroll 4
    for (int i = 0; i < nc; i++) {
        const float* po = g_po + (size_t)(b * NXC + base + i) * 4096 + r * 64 + q4 * 16;
        float wi = w[i];
        #pragma unroll
        for (int v = 0; v < 4; v++) {
            float4 t = *(const float4*)(po + v * 4);
            acc[v].x += t.x * wi; acc[v].y += t.y * wi;
            acc[v].z += t.z * wi; acc[v].w += t.w * wi;
        }
    }
    float* dst = out + ((size_t)b * SEQ + qt * 64 + r) * HD + q4 * 16;
    #pragma unroll
    for (int v = 0; v < 4; v++) {
        acc[v].x *= inv; acc[v].y *= inv; acc[v].z *= inv; acc[v].w *= inv;
        *(float4*)(dst + v * 4) = acc[v];
    }
}

// ---------------------------------------------------------------------------
extern "C" void kernel_launch(void* const* d_in, const int* in_sizes, int n_in,
                              void* d_out, int out_size)
{
    const float* x  = (const float*)d_in[0];
    const float* Wq = (const float*)d_in[1];
    const float* Wk = (const float*)d_in[2];
    const float* Wv = (const float*)d_in[3];
    float* out = (float*)d_out;

    cudaFuncSetAttribute(qkv_mma,
                         cudaFuncAttributeMaxDynamicSharedMemorySize, QKV_SMEM);

    convert_w<<<dim3(64, 3), 256>>>(Wq, Wk, Wv);
    qkv_mma<<<MTOT / 64, 128, QKV_SMEM>>>(x);
    attn_chunk<<<dim3(NXC, BATCH), 128, ATTN_SMEM>>>();
    attn_merge<<<dim3(64, BATCH), 256>>>(out);
}

// round 17
// speedup vs baseline: 1.8630x; 1.0823x over previous
#include <cuda_runtime.h>
#include <cuda_fp16.h>
#include <stdint.h>
#include <math.h>

#define BATCH 4
#define SEQ   4096
#define EMB   1024
#define HD    64
#define MTOT  (BATCH*SEQ)

// fp16 projected q (pre-scaled by 1/32*log2e), k, v hi/lo — device globals
__device__ __half g_q [MTOT*HD];
__device__ __half g_k [MTOT*HD];
__device__ __half g_vh[MTOT*HD];
__device__ __half g_vl[MTOT*HD];

// Pre-converted weights, TRANSPOSED: [o][n=64][k=1024], hi and lo (fp16).
__device__ __half g_wh[3*HD*EMB];
__device__ __half g_wl[3*HD*EMB];

// Split-K attention partials: 160 chunks per batch, 640 total.
#define NXC 160
#define NCHUNK (BATCH*NXC)
__device__ float g_po[NCHUNK*64*64];
__device__ float g_pm[NCHUNK*64];
__device__ float g_pl[NCHUNK*64];

// Single extern shared symbol (char) — cast per kernel.
extern __shared__ char hx_smem[];

// ---------------------------------------------------------------------------
// Helpers
// ---------------------------------------------------------------------------
__device__ __forceinline__ uint32_t smem_u32(const void* p) {
    uint32_t a;
    asm("{ .reg .u64 t; cvta.to.shared.u64 t, %1; cvt.u32.u64 %0, t; }"
        : "=r"(a) : "l"(p));
    return a;
}

__device__ __forceinline__ void ldsm_x4(uint32_t* r, uint32_t addr) {
    asm volatile("ldmatrix.sync.aligned.m8n8.x4.shared.b16 {%0,%1,%2,%3}, [%4];"
        : "=r"(r[0]), "=r"(r[1]), "=r"(r[2]), "=r"(r[3]) : "r"(addr));
}
__device__ __forceinline__ void ldsm_x4_t(uint32_t* r, uint32_t addr) {
    asm volatile("ldmatrix.sync.aligned.m8n8.x4.trans.shared.b16 {%0,%1,%2,%3}, [%4];"
        : "=r"(r[0]), "=r"(r[1]), "=r"(r[2]), "=r"(r[3]) : "r"(addr));
}

// D += A @ B : m16n8k16, fp16 in, fp32 accum
__device__ __forceinline__ void mma16816(float* d, const uint32_t* a,
                                         const uint32_t* b) {
    asm volatile("mma.sync.aligned.m16n8k16.row.col.f32.f16.f16.f32 "
        "{%0,%1,%2,%3}, {%4,%5,%6,%7}, {%8,%9}, {%0,%1,%2,%3};"
        : "+f"(d[0]), "+f"(d[1]), "+f"(d[2]), "+f"(d[3])
        : "r"(a[0]), "r"(a[1]), "r"(a[2]), "r"(a[3]), "r"(b[0]), "r"(b[1]));
}

__device__ __forceinline__ uint32_t pack_h2(float a, float b) {
    __half2 t = __floats2half2_rn(a, b);
    return *(uint32_t*)&t;
}

#define CP_ASYNC16(dst, src) \
    asm volatile("cp.async.cg.shared.global [%0], [%1], 16;" \
                 :: "r"(dst), "l"(src) : "memory")
#define CP_COMMIT() asm volatile("cp.async.commit_group;" ::: "memory")
#define CP_WAIT0()  asm volatile("cp.async.wait_group 0;" ::: "memory")

// chunk-table helpers: chunks of 16 key tiles per q-tile
__device__ __forceinline__ int chunk_base(int qt) {
    if (qt < 16) return qt;
    if (qt < 32) return 16 + 2 * (qt - 16);
    if (qt < 48) return 48 + 3 * (qt - 32);
    return 96 + 4 * (qt - 48);
}

// ---------------------------------------------------------------------------
// Kernel 0: one-shot weight conversion, fp32 [k][n] -> fp16 hi/lo [o][n][k].
// ---------------------------------------------------------------------------
__global__ __launch_bounds__(256) void convert_w(
    const float* __restrict__ Wq,
    const float* __restrict__ Wk,
    const float* __restrict__ Wv)
{
    const int n = blockIdx.x;
    const int o = blockIdx.y;
    const float* W = (o == 0) ? Wq : (o == 1) ? Wk : Wv;
    __half* dh = g_wh + ((size_t)o * HD + n) * EMB;
    __half* dl = g_wl + ((size_t)o * HD + n) * EMB;
    for (int k = threadIdx.x; k < EMB; k += 256) {
        float f = W[(size_t)k * HD + n];
        __half h = __float2half_rn(f);
        dh[k] = h;
        dl[k] = __float2half_rn(f - __half2float(h));
    }
}

// ---------------------------------------------------------------------------
// Kernel 1: QKV projection via warp-level fp16 MMA with hi/lo split (3-term).
// BM=64 rows/CTA, 128 threads (4 warps x m16), grid 256. BK=64.
// q output pre-scaled by (1/sqrt(1024))*log2(e) for base-2 softmax.
// ---------------------------------------------------------------------------
#define BROW 144                       // bytes per smem row (64 fp16 + pad)
#define QOFF_AH 0
#define QOFF_AL (64*BROW)              // 9216
#define QOFF_B  (2*64*BROW)            // 18432; 6 tiles of 64*BROW=9216
#define BTILE   (64*BROW)
#define QKV_SMEM (QOFF_B + 6*BTILE)    // 73728

#define SL2E 0.0450842200f             // 0.03125 * 1.44269504

__global__ __launch_bounds__(128) void qkv_mma(const float* __restrict__ x)
{
    char* smem = hx_smem;
    const uint32_t sb = smem_u32(smem);
    const int tid  = threadIdx.x;
    const int wid  = tid >> 5;
    const int lane = tid & 31;
    const int m0   = blockIdx.x * 64;

    // ldmatrix lane address components
    const int a_row  = lane & 15;
    const int a_koff = (lane >> 4) * 8;          // fp16 elems
    const int b_q    = lane >> 3;
    const int b_r    = lane & 7;
    const int b_nloc = (b_q >> 1) * 8 + b_r;     // n within 16-wide pair
    const int b_koff = (b_q & 1) * 8;

    float acc[3][8][4] = {};

    const __half* wsrc[6] = {
        g_wh + 0 * HD * EMB, g_wl + 0 * HD * EMB,
        g_wh + 1 * HD * EMB, g_wl + 1 * HD * EMB,
        g_wh + 2 * HD * EMB, g_wl + 2 * HD * EMB };

    #pragma unroll 1
    for (int c = 0; c < 16; c++) {
        __syncthreads();   // previous chunk's LDSM reads complete

        // ---- A chunk: X[m0..+63][c*64..+63] -> hi/lo fp16 smem ----
        #pragma unroll
        for (int i = 0; i < 8; i++) {
            int j  = tid + i * 128;          // 0..1023 float4s
            int r  = j >> 4;
            int c4 = (j & 15) * 4;
            float4 v = *(const float4*)(x + (size_t)(m0 + r) * EMB + c * 64 + c4);
            __half h0 = __float2half_rn(v.x);
            __half h1 = __float2half_rn(v.y);
            __half h2 = __float2half_rn(v.z);
            __half h3 = __float2half_rn(v.w);
            __half2 hA = {h0, h1}, hB = {h2, h3};
            __half2 lA = {__float2half_rn(v.x - __half2float(h0)),
                          __float2half_rn(v.y - __half2float(h1))};
            __half2 lB = {__float2half_rn(v.z - __half2float(h2)),
                          __float2half_rn(v.w - __half2float(h3))};
            uint32_t off = (uint32_t)(r * BROW + c4 * 2);
            *(uint2*)(smem + QOFF_AH + off) =
                make_uint2(*(uint32_t*)&hA, *(uint32_t*)&hB);
            *(uint2*)(smem + QOFF_AL + off) =
                make_uint2(*(uint32_t*)&lA, *(uint32_t*)&lB);
        }

        // ---- B tiles: pure uint4 copy from g_wh/g_wl[o][n][c*64..] ----
        #pragma unroll
        for (int i = 0; i < 24; i++) {
            int j    = tid + i * 128;        // 0..3071
            int t    = j >> 9;               // tile 0..5
            int row  = (j >> 3) & 63;        // n
            int seg  = j & 7;                // 8 fp16 per uint4
            *(uint4*)(smem + QOFF_B + t * BTILE + row * BROW + seg * 16) =
                *(const uint4*)(wsrc[t] + (size_t)row * EMB + c * 64 + seg * 8);
        }
        __syncthreads();

        // ---- A fragments: 2 splits x 4 k-steps ----
        uint32_t afr[2][4][4];
        #pragma unroll
        for (int spl = 0; spl < 2; spl++)
            #pragma unroll
            for (int s = 0; s < 4; s++)
                ldsm_x4(afr[spl][s],
                        sb + (spl ? QOFF_AL : QOFF_AH) +
                        (uint32_t)((wid * 16 + a_row) * BROW +
                                   (s * 16 + a_koff) * 2));

        // ---- MMAs: Xh@Wh + Xl@Wh + Xh@Wl ----
        #pragma unroll
        for (int o = 0; o < 3; o++) {
            uint32_t bhb = sb + QOFF_B + (o * 2 + 0) * BTILE;
            uint32_t blb = sb + QOFF_B + (o * 2 + 1) * BTILE;
            #pragma unroll
            for (int s = 0; s < 4; s++) {
                #pragma unroll
                for (int p = 0; p < 4; p++) {
                    uint32_t boff = (uint32_t)((p * 16 + b_nloc) * BROW +
                                               (s * 16 + b_koff) * 2);
                    uint32_t bf[4];
                    ldsm_x4(bf, bhb + boff);
                    mma16816(acc[o][2*p],   afr[0][s], bf);
                    mma16816(acc[o][2*p+1], afr[0][s], bf + 2);
                    mma16816(acc[o][2*p],   afr[1][s], bf);
                    mma16816(acc[o][2*p+1], afr[1][s], bf + 2);
                    ldsm_x4(bf, blb + boff);
                    mma16816(acc[o][2*p],   afr[0][s], bf);
                    mma16816(acc[o][2*p+1], afr[0][s], bf + 2);
                }
            }
        }
    }

    // ---- epilogue: q (pre-scaled), k -> single fp16; v -> fp16 hi/lo ----
    const int g  = lane >> 2;
    const int tg = lane & 3;
    #pragma unroll
    for (int o = 0; o < 3; o++) {
        #pragma unroll
        for (int nt = 0; nt < 8; nt++) {
            int mrow = m0 + wid * 16 + g;
            int ncol = nt * 8 + tg * 2;
            float c0 = acc[o][nt][0], c1 = acc[o][nt][1];
            float c2 = acc[o][nt][2], c3 = acc[o][nt][3];
            if (o == 0) { c0 *= SL2E; c1 *= SL2E; c2 *= SL2E; c3 *= SL2E; }
            __half2 h01 = __floats2half2_rn(c0, c1);
            __half2 h23 = __floats2half2_rn(c2, c3);
            if (o < 2) {
                __half* dst = (o == 0) ? g_q : g_k;
                *(uint32_t*)&dst[(size_t)mrow * HD + ncol]       = *(uint32_t*)&h01;
                *(uint32_t*)&dst[(size_t)(mrow + 8) * HD + ncol] = *(uint32_t*)&h23;
            } else {
                __half2 l01 = __floats2half2_rn(
                    c0 - __half2float(h01.x), c1 - __half2float(h01.y));
                __half2 l23 = __floats2half2_rn(
                    c2 - __half2float(h23.x), c3 - __half2float(h23.y));
                *(uint32_t*)&g_vh[(size_t)mrow * HD + ncol]       = *(uint32_t*)&h01;
                *(uint32_t*)&g_vl[(size_t)mrow * HD + ncol]       = *(uint32_t*)&l01;
                *(uint32_t*)&g_vh[(size_t)(mrow + 8) * HD + ncol] = *(uint32_t*)&h23;
                *(uint32_t*)&g_vl[(size_t)(mrow + 8) * HD + ncol] = *(uint32_t*)&l23;
            }
        }
    }
}

// ---------------------------------------------------------------------------
// Kernel 2: split-K chunked flash attention on fp16 HMMA.
// QK^T: 1 term (S already in log2 units via pre-scaled Q). PV: 3 terms.
// cp.async double-buffered K/V staging, one barrier per tile.
// Grid (160, 4), 128 threads = 4 warps x 16 rows.
// ---------------------------------------------------------------------------
#define ABROW 144
#define ATILE (64*ABROW)          // 9216 bytes per tile array
#define ABUF  (3*ATILE)           // one stage: K,Vh,Vl = 27648
#define ATTN_SMEM (2*ABUF)        // 55296

__global__ __launch_bounds__(128) void attn_chunk()
{
    char* smem = hx_smem;
    const uint32_t sb = smem_u32(smem);
    const int tid  = threadIdx.x;
    const int wid  = tid >> 5;
    const int lane = tid & 31;
    const int g    = lane >> 2;
    const int tg   = lane & 3;

    // big-qt chunks first (LPT)
    const int x = (NXC - 1) - (int)blockIdx.x;
    const int b = blockIdx.y;
    int qt, c;
    if (x < 16)      { qt = x;                 c = 0; }
    else if (x < 48) { qt = 16 + (x - 16) / 2; c = (x - 16) & 1; }
    else if (x < 96) { qt = 32 + (x - 48) / 3; c = (x - 48) % 3; }
    else             { qt = 48 + (x - 96) / 4; c = (x - 96) & 3; }

    const int jt0 = c * 16;
    const int jt1 = min(qt + 1, jt0 + 16);
    const int r0  = qt * 64;
    const size_t tb = (size_t)b * SEQ;

    const __half* bases[3] = {g_k + tb * HD, g_vh + tb * HD, g_vl + tb * HD};

    // staging lane indices
    const int lrow = tid >> 3, lseg = tid & 7;

    // ---- prologue: stage tile jt0 into buf 0 ----
    #pragma unroll
    for (int i = 0; i < 12; i++) {
        int arr = i >> 2;
        int row = (i & 3) * 16 + lrow;
        CP_ASYNC16(sb + arr * ATILE + (uint32_t)(row * ABROW + lseg * 16),
                   bases[arr] + (size_t)(jt0 * 64 + row) * HD + lseg * 8);
    }
    CP_COMMIT();

    // ldmatrix lane addressing
    const int lq  = lane >> 3, lr = lane & 7;
    const int bn  = (lq >> 1) * 8 + lr;       // non-trans B: n row
    const int bk  = (lq & 1) * 8;             //               k offset
    const int trr = (lq & 1) * 8 + lr;        // trans: source row (k)
    const int trc = (lq >> 1) * 8;            //        source col (n)

    const int row_a = r0 + wid * 16 + g;      // global rows this thread owns
    const int row_b = row_a + 8;

    // ---- Q a-frags (single fp16), loaded once from gmem ----
    uint32_t aQ[4][4];
    #pragma unroll
    for (int ks = 0; ks < 4; ks++) {
        size_t ra = (tb + row_a) * HD + ks * 16 + 2 * tg;
        size_t rb = (tb + row_b) * HD + ks * 16 + 2 * tg;
        aQ[ks][0] = *(const uint32_t*)&g_q[ra];
        aQ[ks][1] = *(const uint32_t*)&g_q[rb];
        aQ[ks][2] = *(const uint32_t*)&g_q[ra + 8];
        aQ[ks][3] = *(const uint32_t*)&g_q[rb + 8];
    }

    float oacc[8][4] = {};
    float mA = -1e30f, mB = -1e30f, lA = 0.0f, lB = 0.0f;

    #pragma unroll 1
    for (int jt = jt0; jt < jt1; jt++) {
        const uint32_t bufb = sb + ((jt - jt0) & 1) * ABUF;
        CP_WAIT0();          // tile jt's stage complete
        __syncthreads();     // all warps done with the other buffer

        // ---- issue stage for tile jt+1 into the other buffer ----
        if (jt + 1 < jt1) {
            uint32_t nb = sb + ((jt + 1 - jt0) & 1) * ABUF;
            #pragma unroll
            for (int i = 0; i < 12; i++) {
                int arr = i >> 2;
                int row = (i & 3) * 16 + lrow;
                CP_ASYNC16(nb + arr * ATILE + (uint32_t)(row * ABROW + lseg * 16),
                           bases[arr] + (size_t)((jt + 1) * 64 + row) * HD + lseg * 8);
            }
            CP_COMMIT();
        }

        const int s0 = jt * 64;

        // ---- S = Q K^T (1 term, fp16; already in log2 units) ----
        float sacc[8][4] = {};
        #pragma unroll
        for (int ks = 0; ks < 4; ks++) {
            #pragma unroll
            for (int np = 0; np < 4; np++) {
                uint32_t boff = (uint32_t)((np * 16 + bn) * ABROW +
                                           (ks * 16 + bk) * 2);
                uint32_t bh[4];
                ldsm_x4(bh, bufb + boff);
                mma16816(sacc[2*np],   aQ[ks], bh);
                mma16816(sacc[2*np+1], aQ[ks], bh + 2);
            }
        }

        // ---- causal mask (diag tile only) ----
        if (jt == qt) {
            #pragma unroll
            for (int nt = 0; nt < 8; nt++) {
                int col = s0 + nt * 8 + 2 * tg;
                if (col     > row_a) sacc[nt][0] = -1e30f;
                if (col + 1 > row_a) sacc[nt][1] = -1e30f;
                if (col     > row_b) sacc[nt][2] = -1e30f;
                if (col + 1 > row_b) sacc[nt][3] = -1e30f;
            }
        }

        // ---- online softmax (base 2) ----
        float rmA = -1e30f, rmB = -1e30f;
        #pragma unroll
        for (int nt = 0; nt < 8; nt++) {
            rmA = fmaxf(rmA, fmaxf(sacc[nt][0], sacc[nt][1]));
            rmB = fmaxf(rmB, fmaxf(sacc[nt][2], sacc[nt][3]));
        }
        rmA = fmaxf(rmA, __shfl_xor_sync(0xffffffffu, rmA, 1));
        rmA = fmaxf(rmA, __shfl_xor_sync(0xffffffffu, rmA, 2));
        rmB = fmaxf(rmB, __shfl_xor_sync(0xffffffffu, rmB, 1));
        rmB = fmaxf(rmB, __shfl_xor_sync(0xffffffffu, rmB, 2));

        float mnA = fmaxf(mA, rmA), mnB = fmaxf(mB, rmB);
        float alA = exp2f(mA - mnA), alB = exp2f(mB - mnB);
        mA = mnA; mB = mnB;

        float rsA = 0.0f, rsB = 0.0f;
        uint32_t aPh[4][4], aPl[4][4];
        #pragma unroll
        for (int s4 = 0; s4 < 4; s4++) {
            #pragma unroll
            for (int j = 0; j < 2; j++) {
                int nt = 2 * s4 + j;
                float p0 = exp2f(sacc[nt][0] - mA);
                float p1 = exp2f(sacc[nt][1] - mA);
                float p2 = exp2f(sacc[nt][2] - mB);
                float p3 = exp2f(sacc[nt][3] - mB);
                rsA += p0 + p1; rsB += p2 + p3;
                __half2 h01 = __floats2half2_rn(p0, p1);
                __half2 h23 = __floats2half2_rn(p2, p3);
                aPh[s4][2*j]   = *(uint32_t*)&h01;
                aPh[s4][2*j+1] = *(uint32_t*)&h23;
                aPl[s4][2*j]   = pack_h2(p0 - __half2float(h01.x),
                                         p1 - __half2float(h01.y));
                aPl[s4][2*j+1] = pack_h2(p2 - __half2float(h23.x),
                                         p3 - __half2float(h23.y));
            }
        }
        rsA += __shfl_xor_sync(0xffffffffu, rsA, 1);
        rsA += __shfl_xor_sync(0xffffffffu, rsA, 2);
        rsB += __shfl_xor_sync(0xffffffffu, rsB, 1);
        rsB += __shfl_xor_sync(0xffffffffu, rsB, 2);
        lA = lA * alA + rsA;
        lB = lB * alB + rsB;

        #pragma unroll
        for (int ht = 0; ht < 8; ht++) {
            oacc[ht][0] *= alA; oacc[ht][1] *= alA;
            oacc[ht][2] *= alB; oacc[ht][3] *= alB;
        }

        // ---- O += P V (3-term hi/lo), V b-frags via ldmatrix.trans ----
        #pragma unroll
        for (int ks = 0; ks < 4; ks++) {
            #pragma unroll
            for (int hp = 0; hp < 4; hp++) {
                uint32_t taddr = bufb + 1 * ATILE +
                    (uint32_t)((ks * 16 + trr) * ABROW + (hp * 16 + trc) * 2);
                uint32_t vh4[4], vl4[4];
                ldsm_x4_t(vh4, taddr);
                ldsm_x4_t(vl4, taddr + ATILE);
                mma16816(oacc[2*hp],   aPh[ks], vh4);
                mma16816(oacc[2*hp+1], aPh[ks], vh4 + 2);
                mma16816(oacc[2*hp],   aPl[ks], vh4);
                mma16816(oacc[2*hp+1], aPl[ks], vh4 + 2);
                mma16816(oacc[2*hp],   aPh[ks], vl4);
                mma16816(oacc[2*hp+1], aPh[ks], vl4 + 2);
            }
        }
    }

    // ---- store unnormalized partial (O, m, l) ----
    const int cid = b * NXC + x;
    float* po = g_po + (size_t)cid * 4096;
    const int la = wid * 16 + g;      // local row a
    #pragma unroll
    for (int ht = 0; ht < 8; ht++) {
        int col = ht * 8 + 2 * tg;
        *(float2*)&po[la * 64 + col]       = make_float2(oacc[ht][0], oacc[ht][1]);
        *(float2*)&po[(la + 8) * 64 + col] = make_float2(oacc[ht][2], oacc[ht][3]);
    }
    if (tg == 0) {
        g_pm[cid * 64 + la]     = mA;
        g_pm[cid * 64 + la + 8] = mB;
        g_pl[cid * 64 + la]     = lA;
        g_pl[cid * 64 + la + 8] = lB;
    }
}

// ---------------------------------------------------------------------------
// Kernel 3: merge partial chunks. Grid (64, 4) = (qt, b), 256 threads.
// Weights in base-2 (m values are log2-domain).
// ---------------------------------------------------------------------------
__global__ __launch_bounds__(256) void attn_merge(float* __restrict__ out)
{
    const int qt = blockIdx.x;
    const int b  = blockIdx.y;
    const int nc = qt / 16 + 1;
    const int base = chunk_base(qt);

    const int r  = threadIdx.x >> 2;
    const int q4 = threadIdx.x & 3;

    float m[4], l[4];
    float M = -1e30f;
    #pragma unroll 4
    for (int i = 0; i < nc; i++) {
        int cid = b * NXC + base + i;
        m[i] = g_pm[cid * 64 + r];
        l[i] = g_pl[cid * 64 + r];
        M = fmaxf(M, m[i]);
    }
    float denom = 0.0f;
    float w[4];
    #pragma unroll 4
    for (int i = 0; i < nc; i++) {
        w[i] = exp2f(m[i] - M);
        denom += l[i] * w[i];
    }
    float inv = 1.0f / denom;

    float4 acc[4] = {};
    #pragma unroll 4
    for (int i = 0; i < nc; i++) {
        const float* po = g_po + (size_t)(b * NXC + base + i) * 4096 + r * 64 + q4 * 16;
        float wi = w[i];
        #pragma unroll
        for (int v = 0; v < 4; v++) {
            float4 t = *(const float4*)(po + v * 4);
            acc[v].x += t.x * wi; acc[v].y += t.y * wi;
            acc[v].z += t.z * wi; acc[v].w += t.w * wi;
        }
    }
    float* dst = out + ((size_t)b * SEQ + qt * 64 + r) * HD + q4 * 16;
    #pragma unroll
    for (int v = 0; v < 4; v++) {
        acc[v].x *= inv; acc[v].y *= inv; acc[v].z *= inv; acc[v].w *= inv;
        *(float4*)(dst + v * 4) = acc[v];
    }
}

// ---------------------------------------------------------------------------
extern "C" void kernel_launch(void* const* d_in, const int* in_sizes, int n_in,
                              void* d_out, int out_size)
{
    const float* x  = (const float*)d_in[0];
    const float* Wq = (const float*)d_in[1];
    const float* Wk = (const float*)d_in[2];
    const float* Wv = (const float*)d_in[3];
    float* out = (float*)d_out;

    cudaFuncSetAttribute(qkv_mma,
                         cudaFuncAttributeMaxDynamicSharedMemorySize, QKV_SMEM);
    cudaFuncSetAttribute(attn_chunk,
                         cudaFuncAttributeMaxDynamicSharedMemorySize, ATTN_SMEM);

    convert_w<<<dim3(64, 3), 256>>>(Wq, Wk, Wv);
    qkv_mma<<<MTOT / 64, 128, QKV_SMEM>>>(x);
    attn_chunk<<<dim3(NXC, BATCH), 128, ATTN_SMEM>>>();
    attn_merge<<<dim3(64, BATCH), 256>>>(out);
}